// round 7
// baseline (speedup 1.0000x reference)
#include <cuda_runtime.h>
#include <cuda_bf16.h>
#include <cstdint>

#define B_  4
#define S_  2048
#define D_  1024
#define H_  16
#define DH_ 64
#define M_  (B_*S_)   // 8192

// ---------------- scratch (static __device__, no allocation) ----------------
__device__ __nv_bfloat16 g_Qhi[(size_t)M_*D_];   // [B,H,S,DH]
__device__ __nv_bfloat16 g_Qlo[(size_t)M_*D_];
__device__ __nv_bfloat16 g_Khi[(size_t)M_*D_];
__device__ __nv_bfloat16 g_Klo[(size_t)M_*D_];
__device__ __nv_bfloat16 g_Vhi[(size_t)M_*D_];
__device__ __nv_bfloat16 g_Vlo[(size_t)M_*D_];
__device__ __nv_bfloat16 g_AOhi[(size_t)M_*D_]; // [B*S, D] merged heads
__device__ __nv_bfloat16 g_AOlo[(size_t)M_*D_];
__device__ __nv_bfloat16 g_xhi[(size_t)M_*D_];
__device__ __nv_bfloat16 g_xlo[(size_t)M_*D_];
__device__ __nv_bfloat16 g_Whi[4][(size_t)D_*D_];
__device__ __nv_bfloat16 g_Wlo[4][(size_t)D_*D_];

// ---------------------------------------------------------------------------
__device__ __forceinline__ void split2(float x, float y, uint32_t& hi, uint32_t& lo) {
    __nv_bfloat16 hx = __float2bfloat16_rn(x);
    __nv_bfloat16 hy = __float2bfloat16_rn(y);
    __nv_bfloat16 lx = __float2bfloat16_rn(x - __bfloat162float(hx));
    __nv_bfloat16 ly = __float2bfloat16_rn(y - __bfloat162float(hy));
    __nv_bfloat162 Hv(hx, hy), Lv(lx, ly);
    hi = *(uint32_t*)&Hv;
    lo = *(uint32_t*)&Lv;
}

// ---------------------------------------------------------------------------
// fused split conversion: x (2M float4) then 4 weights (256K float4 each)
// ---------------------------------------------------------------------------
#define NX4 ((M_*D_)/4)     // 2M
#define NW4 ((D_*D_)/4)     // 256K

__global__ __launch_bounds__(256) void cvt_split_all(const float4* __restrict__ x,
                                                     const float4* __restrict__ w0,
                                                     const float4* __restrict__ w1,
                                                     const float4* __restrict__ w2,
                                                     const float4* __restrict__ w3) {
    int i = blockIdx.x * blockDim.x + threadIdx.x;
    const float4* src;
    __nv_bfloat162 *hi, *lo;
    int idx;
    if (i < NX4) {
        src = x; idx = i;
        hi = (__nv_bfloat162*)g_xhi; lo = (__nv_bfloat162*)g_xlo;
    } else {
        int j = i - NX4;
        int w = j / NW4; idx = j - w * NW4;
        src = (w == 0) ? w0 : (w == 1) ? w1 : (w == 2) ? w2 : w3;
        hi = (__nv_bfloat162*)(g_Whi[0] + (size_t)w * D_ * D_);
        lo = (__nv_bfloat162*)(g_Wlo[0] + (size_t)w * D_ * D_);
    }
    float4 v = src[idx];
    uint32_t h0, l0v, h1, l1v;
    split2(v.x, v.y, h0, l0v);
    split2(v.z, v.w, h1, l1v);
    ((uint32_t*)hi)[2*idx]   = h0;
    ((uint32_t*)hi)[2*idx+1] = h1;
    ((uint32_t*)lo)[2*idx]   = l0v;
    ((uint32_t*)lo)[2*idx+1] = l1v;
}

// ---------------------------------------------------------------------------
// common PTX macros
// ---------------------------------------------------------------------------
#define CP16(dst, src) \
    asm volatile("cp.async.cg.shared.global [%0], [%1], 16;\n" :: "r"(dst), "l"(src))
#define CP_COMMIT() asm volatile("cp.async.commit_group;\n" ::: "memory")
#define CP_WAIT(n)  asm volatile("cp.async.wait_group %0;\n" :: "n"(n) : "memory")

#define LDM_X4(r0,r1,r2,r3, addr) \
    asm volatile("ldmatrix.sync.aligned.m8n8.x4.shared.b16 {%0,%1,%2,%3}, [%4];" \
                 : "=r"(r0),"=r"(r1),"=r"(r2),"=r"(r3) : "r"(addr))
#define LDM_X2(r0,r1, addr) \
    asm volatile("ldmatrix.sync.aligned.m8n8.x2.shared.b16 {%0,%1}, [%2];" \
                 : "=r"(r0),"=r"(r1) : "r"(addr))
#define LDM_X2T(r0,r1, addr) \
    asm volatile("ldmatrix.sync.aligned.m8n8.x2.trans.shared.b16 {%0,%1}, [%2];" \
                 : "=r"(r0),"=r"(r1) : "r"(addr))

#define MMA16816(c0,c1,c2,c3, a0,a1,a2,a3, b0,b1) \
    asm volatile("mma.sync.aligned.m16n8k16.row.col.f32.bf16.bf16.f32 " \
                 "{%0,%1,%2,%3}, {%4,%5,%6,%7}, {%8,%9}, {%0,%1,%2,%3};" \
                 : "+f"(c0),"+f"(c1),"+f"(c2),"+f"(c3) \
                 : "r"(a0),"r"(a1),"r"(a2),"r"(a3),"r"(b0),"r"(b1))

// ---------------------------------------------------------------------------
// bf16x3 split GEMM, 4-stage cp.async pipeline, one barrier per k-step.
// C[m,n] = sum_k A[m,k]*W[n,k] + bias[n]
// 128x128 CTA tile, BK=16 per stage, 256 threads (8 warps = 2m x 4n),
// warp tile 64x32.  Smem pitch 48B (3 x 16B chunks, odd -> conflict-free).
// QKV launch: gridDim.z=3, mode=z (split-store [B,H,S,DH]); O: mode 3 fp32.
// ---------------------------------------------------------------------------
#define GBK   16
#define GPITCH 24                 // bf16 per smem row (48 bytes)
#define GTILE (128*GPITCH*2)      // 6144 B
#define GSTAGE (4*GTILE)          // 24576 B: Ahi, Alo, Bhi, Blo
#define GNST  4
#define GSMEM (GNST*GSTAGE)       // 98304 B
#define GITERS (D_/GBK)           // 64

// stage loader: 4 tiles x 128 rows x 2 chunks(16B) = 1024 chunks, 256 thr x 4
#define GLOAD(st, kb) do {                                                    \
    _Pragma("unroll")                                                         \
    for (int i_ = 0; i_ < 4; i_++) {                                          \
        int c_ = tid + (i_ << 8);                                             \
        int t_ = c_ >> 8;                                                     \
        int r_ = (c_ >> 1) & 127;                                             \
        int ch_ = c_ & 1;                                                     \
        uint32_t dst_ = smBase + (uint32_t)((st) * GSTAGE + t_ * GTILE        \
                                            + r_ * (GPITCH*2) + ch_ * 16);    \
        const __nv_bfloat16* s_ = (t_ == 0) ? Ahi : (t_ == 1) ? Alo           \
                                 : (t_ == 2) ? Bhi : Blo;                     \
        size_t g_ = (size_t)(((t_ < 2) ? mBase : nBase) + r_) * D_            \
                    + (kb) + ch_ * 8;                                         \
        CP16(dst_, s_ + g_);                                                  \
    }                                                                         \
    CP_COMMIT();                                                              \
} while (0)

extern "C" __global__ __launch_bounds__(256) void gemm_bf16x3(
    const __nv_bfloat16* __restrict__ Ahi, const __nv_bfloat16* __restrict__ Alo,
    const __nv_bfloat16* __restrict__ WhiB, const __nv_bfloat16* __restrict__ WloB,
    const float* __restrict__ b0p, const float* __restrict__ b1p,
    const float* __restrict__ b2p, float* __restrict__ outp, int mode_base)
{
    extern __shared__ __nv_bfloat16 sm[];
    const int zi = blockIdx.z;
    const int mode = mode_base ? 3 : zi;
    const __nv_bfloat16* Bhi = WhiB + (size_t)zi * D_ * D_;
    const __nv_bfloat16* Blo = WloB + (size_t)zi * D_ * D_;
    const float* bias = (zi == 0) ? b0p : (zi == 1) ? b1p : b2p;

    const int tid  = threadIdx.x;
    const int wid  = tid >> 5, lane = tid & 31;
    const int wm   = wid >> 2, wn = wid & 3;
    const int mBase = blockIdx.y * 128;
    const int nBase = blockIdx.x * 128;
    const uint32_t smBase = (uint32_t)__cvta_generic_to_shared(sm);

    float c[4][4][4];
    #pragma unroll
    for (int mi = 0; mi < 4; mi++)
        #pragma unroll
        for (int ni = 0; ni < 4; ni++)
            #pragma unroll
            for (int e = 0; e < 4; e++) c[mi][ni][e] = 0.f;

    const int aRow = (lane & 7) + ((lane >> 3) & 1) * 8;
    const int aK   = (lane >> 4) * 8;
    const int bRow = lane & 7;
    const int bK   = ((lane >> 3) & 1) * 8;

    // prologue: 3 stages in flight
    GLOAD(0, 0);
    GLOAD(1, GBK);
    GLOAD(2, 2 * GBK);

    for (int s = 0; s < GITERS; s++) {
        CP_WAIT(2);            // stage s landed (3 groups outstanding at entry)
        __syncthreads();       // all warps past compute of s-1; data visible

        // refill the buffer consumed at s-1 with stage s+3 (or keep invariant)
        if (s + 3 < GITERS) {
            GLOAD((s + 3) & 3, (s + 3) * GBK);
        } else {
            CP_COMMIT();       // empty group keeps wait-count invariant
        }

        const uint32_t stBase = smBase + (uint32_t)((s & 3) * GSTAGE);
        uint32_t ah[4][4], al[4][4], bh[4][2], bl[4][2];
        #pragma unroll
        for (int mi = 0; mi < 4; mi++) {
            int row = wm * 64 + mi * 16 + aRow;
            uint32_t off = stBase + (uint32_t)(row * GPITCH + aK) * 2;
            LDM_X4(ah[mi][0], ah[mi][1], ah[mi][2], ah[mi][3], off);
            LDM_X4(al[mi][0], al[mi][1], al[mi][2], al[mi][3], off + GTILE);
        }
        #pragma unroll
        for (int ni = 0; ni < 4; ni++) {
            int row = wn * 32 + ni * 8 + bRow;
            uint32_t off = stBase + 2 * GTILE + (uint32_t)(row * GPITCH + bK) * 2;
            LDM_X2(bh[ni][0], bh[ni][1], off);
            LDM_X2(bl[ni][0], bl[ni][1], off + GTILE);
        }
        #pragma unroll
        for (int mi = 0; mi < 4; mi++)
            #pragma unroll
            for (int ni = 0; ni < 4; ni++) {
                MMA16816(c[mi][ni][0], c[mi][ni][1], c[mi][ni][2], c[mi][ni][3],
                         ah[mi][0], ah[mi][1], ah[mi][2], ah[mi][3],
                         bh[ni][0], bh[ni][1]);
                MMA16816(c[mi][ni][0], c[mi][ni][1], c[mi][ni][2], c[mi][ni][3],
                         ah[mi][0], ah[mi][1], ah[mi][2], ah[mi][3],
                         bl[ni][0], bl[ni][1]);
                MMA16816(c[mi][ni][0], c[mi][ni][1], c[mi][ni][2], c[mi][ni][3],
                         al[mi][0], al[mi][1], al[mi][2], al[mi][3],
                         bh[ni][0], bh[ni][1]);
            }
    }

    // ---------------- epilogue ----------------
    const int g  = lane >> 2;
    const int th = lane & 3;

    if (mode == 3) {
        #pragma unroll
        for (int mi = 0; mi < 4; mi++)
            #pragma unroll
            for (int ni = 0; ni < 4; ni++) {
                int row0 = mBase + wm * 64 + mi * 16 + g;
                int col0 = nBase + wn * 32 + ni * 8 + th * 2;
                #pragma unroll
                for (int e = 0; e < 4; e++) {
                    int m = row0 + (e >> 1) * 8;
                    int n = col0 + (e & 1);
                    outp[(size_t)m * D_ + n] = c[mi][ni][e] + bias[n];
                }
            }
    } else {
        __nv_bfloat16* dhi = (mode == 0) ? g_Qhi : (mode == 1) ? g_Khi : g_Vhi;
        __nv_bfloat16* dlo = (mode == 0) ? g_Qlo : (mode == 1) ? g_Klo : g_Vlo;
        #pragma unroll
        for (int mi = 0; mi < 4; mi++)
            #pragma unroll
            for (int ni = 0; ni < 4; ni++) {
                int row0 = mBase + wm * 64 + mi * 16 + g;
                int col0 = nBase + wn * 32 + ni * 8 + th * 2;
                float b0v = bias[col0], b1v = bias[col0 + 1];
                int hh = col0 >> 6, dh = col0 & 63;
                #pragma unroll
                for (int pr = 0; pr < 2; pr++) {
                    int m = row0 + pr * 8;
                    int b = m >> 11, s = m & 2047;
                    float v0 = c[mi][ni][pr*2]   + b0v;
                    float v1 = c[mi][ni][pr*2+1] + b1v;
                    uint32_t hv, lv;
                    split2(v0, v1, hv, lv);
                    size_t idx = (((size_t)(b * H_ + hh)) * S_ + s) * DH_ + dh;
                    *(uint32_t*)&dhi[idx] = hv;
                    *(uint32_t*)&dlo[idx] = lv;
                }
            }
    }
}

// ---------------------------------------------------------------------------
// Tensor-core flash attention (causal), bf16x3, BQ=128, 8 warps,
// 3-stage K/V pipeline, ONE barrier per key-tile, per-warp causal skip.
// ---------------------------------------------------------------------------
#define LDF 72
#define FTILEB (64*LDF*2)      // 9216 B per 64-row tile
#define QTILEB (128*LDF*2)     // 18432 B per 128-row Q tile
#define FSTAGE (4*FTILEB)      // 36864 B: Khi, Klo, Vhi, Vlo
#define FNST   3
#define FSMEM  (FNST*FSTAGE)   // 110592 B dynamic

__global__ __launch_bounds__(256) void flash_tc() {
    extern __shared__ __nv_bfloat16 fsm[];
    const uint32_t smBase = (uint32_t)__cvta_generic_to_shared(fsm);

    const int bh = blockIdx.y;
    const int Qb = blockIdx.x;
    const int q0 = Qb * 128;
    const int tid  = threadIdx.x;
    const int wq   = tid >> 5, lane = tid & 31;
    const int g    = lane >> 2, th = lane & 3;

    const size_t base = (size_t)bh * S_ * DH_;
    const __nv_bfloat16* Qh = g_Qhi + base;
    const __nv_bfloat16* Ql = g_Qlo + base;
    const __nv_bfloat16* Kh = g_Khi + base;
    const __nv_bfloat16* Kl = g_Klo + base;
    const __nv_bfloat16* Vh = g_Vhi + base;
    const __nv_bfloat16* Vl = g_Vlo + base;

    // ---- stage Q (hi+lo = 36864 B) into buffer 0, pull frags ----
    #pragma unroll
    for (int i = 0; i < 8; i++) {
        int c = tid + i * 256;
        int t = c >> 10, r = (c >> 3) & 127, c8 = c & 7;
        const __nv_bfloat16* src = (t ? Ql : Qh) + (size_t)(q0 + r) * DH_ + c8 * 8;
        CP16(smBase + (uint32_t)(t * QTILEB + r * (LDF*2) + c8 * 16), src);
    }
    CP_COMMIT();
    CP_WAIT(0);
    __syncthreads();

    uint32_t qh[4][4], ql[4][4];
    {
        const int aRow = lane & 15, aK = (lane >> 4) * 8;
        int row = wq * 16 + aRow;
        #pragma unroll
        for (int j = 0; j < 4; j++) {
            uint32_t off = smBase + (uint32_t)(row * LDF + j * 16 + aK) * 2;
            LDM_X4(qh[j][0], qh[j][1], qh[j][2], qh[j][3], off);
            LDM_X4(ql[j][0], ql[j][1], ql[j][2], ql[j][3], off + QTILEB);
        }
    }
    __syncthreads();   // Q frags read before tile loads overwrite buffer 0

    float m0 = -1e30f, m1 = -1e30f, l0 = 0.f, l1 = 0.f;
    float co[8][4];
    #pragma unroll
    for (int nt = 0; nt < 8; nt++)
        #pragma unroll
        for (int e = 0; e < 4; e++) co[nt][e] = 0.f;

    const int bRow  = lane & 7;
    const int bK    = ((lane >> 3) & 1) * 8;
    const int vRow0 = (lane & 7) + ((lane >> 3) & 1) * 8;
    const int wmaxq = q0 + wq * 16 + 15;

    const int NT = 2 * Qb + 2;

#define FLOAD(st, ktv) do {                                                       \
    _Pragma("unroll")                                                             \
    for (int i_ = 0; i_ < 8; i_++) {                                              \
        int c_ = tid + i_ * 256;                                                  \
        int t_ = c_ >> 9, r_ = (c_ >> 3) & 63, c8_ = c_ & 7;                      \
        const __nv_bfloat16* s_ = (t_ == 0) ? Kh : (t_ == 1) ? Kl                 \
                                 : (t_ == 2) ? Vh : Vl;                           \
        CP16(smBase + (uint32_t)((st) * FSTAGE + t_ * FTILEB                      \
                                 + r_ * (LDF*2) + c8_ * 16),                      \
             s_ + (size_t)((ktv) * 64 + r_) * DH_ + c8_ * 8);                     \
    }                                                                             \
    CP_COMMIT();                                                                  \
} while (0)

    // prologue: 2 tiles in flight
    FLOAD(0, 0);
    FLOAD(1, 1);   // NT >= 2 always

    for (int kt = 0; kt < NT; kt++) {
        CP_WAIT(1);            // tile kt landed (2 groups outstanding at entry)
        __syncthreads();       // all warps past compute of kt-1

        if (kt + 2 < NT) {
            FLOAD((kt + 2) % 3, kt + 2);   // refills buffer consumed at kt-1
        } else {
            CP_COMMIT();
        }

        if (kt * 64 <= wmaxq) {
            const uint32_t smK = smBase + (uint32_t)((kt % 3) * FSTAGE);
            const uint32_t smV = smK + 2 * FTILEB;

            float cs[8][4];
            #pragma unroll
            for (int nt = 0; nt < 8; nt++)
                #pragma unroll
                for (int e = 0; e < 4; e++) cs[nt][e] = 0.f;

            #pragma unroll
            for (int nt = 0; nt < 8; nt++) {
                #pragma unroll
                for (int j = 0; j < 4; j++) {
                    uint32_t off = smK + (uint32_t)((nt*8 + bRow) * LDF + j*16 + bK) * 2;
                    uint32_t k0, k1, k2, k3;
                    LDM_X2(k0, k1, off);
                    LDM_X2(k2, k3, off + FTILEB);
                    MMA16816(cs[nt][0], cs[nt][1], cs[nt][2], cs[nt][3],
                             qh[j][0], qh[j][1], qh[j][2], qh[j][3], k0, k1);
                    MMA16816(cs[nt][0], cs[nt][1], cs[nt][2], cs[nt][3],
                             qh[j][0], qh[j][1], qh[j][2], qh[j][3], k2, k3);
                    MMA16816(cs[nt][0], cs[nt][1], cs[nt][2], cs[nt][3],
                             ql[j][0], ql[j][1], ql[j][2], ql[j][3], k0, k1);
                }
            }

            const float scale = 0.125f;
            if (kt * 64 + 63 > q0 + wq * 16) {
                #pragma unroll
                for (int nt = 0; nt < 8; nt++) {
                    int kn = kt * 64 + nt * 8 + th * 2;
                    #pragma unroll
                    for (int e = 0; e < 4; e++) {
                        int kidx = kn + (e & 1);
                        int qi   = q0 + wq * 16 + g + (e >> 1) * 8;
                        cs[nt][e] = (kidx <= qi) ? cs[nt][e] * scale : -1e30f;
                    }
                }
            } else {
                #pragma unroll
                for (int nt = 0; nt < 8; nt++)
                    #pragma unroll
                    for (int e = 0; e < 4; e++) cs[nt][e] *= scale;
            }

            float tm0 = -1e30f, tm1 = -1e30f;
            #pragma unroll
            for (int nt = 0; nt < 8; nt++) {
                tm0 = fmaxf(tm0, fmaxf(cs[nt][0], cs[nt][1]));
                tm1 = fmaxf(tm1, fmaxf(cs[nt][2], cs[nt][3]));
            }
            tm0 = fmaxf(tm0, __shfl_xor_sync(0xffffffffu, tm0, 1));
            tm0 = fmaxf(tm0, __shfl_xor_sync(0xffffffffu, tm0, 2));
            tm1 = fmaxf(tm1, __shfl_xor_sync(0xffffffffu, tm1, 1));
            tm1 = fmaxf(tm1, __shfl_xor_sync(0xffffffffu, tm1, 2));

            float mn0 = fmaxf(m0, tm0), mn1 = fmaxf(m1, tm1);
            float cr0 = __expf(m0 - mn0), cr1 = __expf(m1 - mn1);
            m0 = mn0; m1 = mn1;
            l0 *= cr0; l1 *= cr1;
            #pragma unroll
            for (int nt = 0; nt < 8; nt++) {
                co[nt][0] *= cr0; co[nt][1] *= cr0;
                co[nt][2] *= cr1; co[nt][3] *= cr1;
            }

            uint32_t ah[4][4], al[4][4];
            #pragma unroll
            for (int nt = 0; nt < 8; nt++) {
                float p0 = __expf(cs[nt][0] - m0);
                float p1 = __expf(cs[nt][1] - m0);
                float p2 = __expf(cs[nt][2] - m1);
                float p3 = __expf(cs[nt][3] - m1);
                l0 += p0 + p1;
                l1 += p2 + p3;
                int j = nt >> 1, hh = (nt & 1) * 2;
                split2(p0, p1, ah[j][hh],     al[j][hh]);      // row g,   keys k..k+1
                split2(p2, p3, ah[j][hh + 1], al[j][hh + 1]);  // row g+8, keys k..k+1
            }

            #pragma unroll
            for (int nt = 0; nt < 8; nt++) {
                #pragma unroll
                for (int j = 0; j < 4; j++) {
                    uint32_t off = smV + (uint32_t)((j*16 + vRow0) * LDF + nt*8) * 2;
                    uint32_t v0, v1, w0, w1;
                    LDM_X2T(v0, v1, off);
                    LDM_X2T(w0, w1, off + FTILEB);
                    MMA16816(co[nt][0], co[nt][1], co[nt][2], co[nt][3],
                             ah[j][0], ah[j][1], ah[j][2], ah[j][3], v0, v1);
                    MMA16816(co[nt][0], co[nt][1], co[nt][2], co[nt][3],
                             ah[j][0], ah[j][1], ah[j][2], ah[j][3], w0, w1);
                    MMA16816(co[nt][0], co[nt][1], co[nt][2], co[nt][3],
                             al[j][0], al[j][1], al[j][2], al[j][3], v0, v1);
                }
            }
        }
    }

    l0 += __shfl_xor_sync(0xffffffffu, l0, 1);
    l0 += __shfl_xor_sync(0xffffffffu, l0, 2);
    l1 += __shfl_xor_sync(0xffffffffu, l1, 1);
    l1 += __shfl_xor_sync(0xffffffffu, l1, 2);
    float inv0 = 1.f / l0, inv1 = 1.f / l1;

    const int b  = bh >> 4, hh = bh & 15;
    const int r0 = q0 + wq * 16 + g;
    #pragma unroll
    for (int nt = 0; nt < 8; nt++) {
        int dh = nt * 8 + th * 2;
        size_t i0 = ((size_t)(b * S_ + r0))     * D_ + hh * DH_ + dh;
        size_t i1 = ((size_t)(b * S_ + r0 + 8)) * D_ + hh * DH_ + dh;
        uint32_t hv, lv;
        split2(co[nt][0] * inv0, co[nt][1] * inv0, hv, lv);
        *(uint32_t*)&g_AOhi[i0] = hv;
        *(uint32_t*)&g_AOlo[i0] = lv;
        split2(co[nt][2] * inv1, co[nt][3] * inv1, hv, lv);
        *(uint32_t*)&g_AOhi[i1] = hv;
        *(uint32_t*)&g_AOlo[i1] = lv;
    }
#undef FLOAD
}

// ---------------------------------------------------------------------------
extern "C" void kernel_launch(void* const* d_in, const int* in_sizes, int n_in,
                              void* d_out, int out_size) {
    const float* x  = (const float*)d_in[0];
    const float* Wq = (const float*)d_in[1];
    const float* bq = (const float*)d_in[2];
    const float* Wk = (const float*)d_in[3];
    const float* bk = (const float*)d_in[4];
    const float* Wv = (const float*)d_in[5];
    const float* bv = (const float*)d_in[6];
    const float* Wo = (const float*)d_in[7];
    const float* bo = (const float*)d_in[8];
    float* out = (float*)d_out;

    cudaFuncSetAttribute(gemm_bf16x3, cudaFuncAttributeMaxDynamicSharedMemorySize,
                         GSMEM);
    cudaFuncSetAttribute(flash_tc, cudaFuncAttributeMaxDynamicSharedMemorySize,
                         FSMEM);

    __nv_bfloat16 *xhi, *xlo, *aohi, *aolo, *whi, *wlo;
    cudaGetSymbolAddress((void**)&xhi,  g_xhi);
    cudaGetSymbolAddress((void**)&xlo,  g_xlo);
    cudaGetSymbolAddress((void**)&aohi, g_AOhi);
    cudaGetSymbolAddress((void**)&aolo, g_AOlo);
    cudaGetSymbolAddress((void**)&whi,  g_Whi);
    cudaGetSymbolAddress((void**)&wlo,  g_Wlo);

    const int ntot = NX4 + 4 * NW4;
    cvt_split_all<<<(ntot + 255) / 256, 256>>>((const float4*)x,
        (const float4*)Wq, (const float4*)Wk, (const float4*)Wv, (const float4*)Wo);

    // fused QKV projection (gridDim.z = 3)
    dim3 gq(D_ / 128, M_ / 128, 3);
    gemm_bf16x3<<<gq, 256, GSMEM>>>(xhi, xlo, whi, wlo, bq, bk, bv, nullptr, 0);

    dim3 fg(S_ / 128, B_ * H_);  // (16, 64)
    flash_tc<<<fg, 256, FSMEM>>>();

    // O projection
    dim3 go(D_ / 128, M_ / 128, 1);
    gemm_bf16x3<<<go, 256, GSMEM>>>(aohi, aolo,
        whi + 3 * (size_t)D_ * D_, wlo + 3 * (size_t)D_ * D_,
        bo, bo, bo, out, 3);
}

// round 8
// speedup vs baseline: 1.0593x; 1.0593x over previous
#include <cuda_runtime.h>
#include <cuda_bf16.h>
#include <cstdint>

#define B_  4
#define S_  2048
#define D_  1024
#define H_  16
#define DH_ 64
#define M_  (B_*S_)   // 8192

// ---------------- scratch (static __device__, no allocation) ----------------
__device__ __nv_bfloat16 g_Qhi[(size_t)M_*D_];   // [B,H,S,DH]
__device__ __nv_bfloat16 g_Qlo[(size_t)M_*D_];
__device__ __nv_bfloat16 g_Khi[(size_t)M_*D_];
__device__ __nv_bfloat16 g_Klo[(size_t)M_*D_];
__device__ __nv_bfloat16 g_Vhi[(size_t)M_*D_];
__device__ __nv_bfloat16 g_Vlo[(size_t)M_*D_];
__device__ __nv_bfloat16 g_AOhi[(size_t)M_*D_]; // [B*S, D] merged heads
__device__ __nv_bfloat16 g_AOlo[(size_t)M_*D_];
__device__ __nv_bfloat16 g_xhi[(size_t)M_*D_];
__device__ __nv_bfloat16 g_xlo[(size_t)M_*D_];
__device__ __nv_bfloat16 g_Whi[4][(size_t)D_*D_];
__device__ __nv_bfloat16 g_Wlo[4][(size_t)D_*D_];

// ---------------------------------------------------------------------------
__device__ __forceinline__ void split2(float x, float y, uint32_t& hi, uint32_t& lo) {
    __nv_bfloat16 hx = __float2bfloat16_rn(x);
    __nv_bfloat16 hy = __float2bfloat16_rn(y);
    __nv_bfloat16 lx = __float2bfloat16_rn(x - __bfloat162float(hx));
    __nv_bfloat16 ly = __float2bfloat16_rn(y - __bfloat162float(hy));
    __nv_bfloat162 Hv(hx, hy), Lv(lx, ly);
    hi = *(uint32_t*)&Hv;
    lo = *(uint32_t*)&Lv;
}

// ---------------------------------------------------------------------------
// fused split conversion: x (2M float4) then 4 weights (256K float4 each)
// ---------------------------------------------------------------------------
#define NX4 ((M_*D_)/4)     // 2M
#define NW4 ((D_*D_)/4)     // 256K

__global__ __launch_bounds__(256) void cvt_split_all(const float4* __restrict__ x,
                                                     const float4* __restrict__ w0,
                                                     const float4* __restrict__ w1,
                                                     const float4* __restrict__ w2,
                                                     const float4* __restrict__ w3) {
    int i = blockIdx.x * blockDim.x + threadIdx.x;
    const float4* src;
    __nv_bfloat162 *hi, *lo;
    int idx;
    if (i < NX4) {
        src = x; idx = i;
        hi = (__nv_bfloat162*)g_xhi; lo = (__nv_bfloat162*)g_xlo;
    } else {
        int j = i - NX4;
        int w = j / NW4; idx = j - w * NW4;
        src = (w == 0) ? w0 : (w == 1) ? w1 : (w == 2) ? w2 : w3;
        hi = (__nv_bfloat162*)(g_Whi[0] + (size_t)w * D_ * D_);
        lo = (__nv_bfloat162*)(g_Wlo[0] + (size_t)w * D_ * D_);
    }
    float4 v = src[idx];
    uint32_t h0, l0v, h1, l1v;
    split2(v.x, v.y, h0, l0v);
    split2(v.z, v.w, h1, l1v);
    ((uint32_t*)hi)[2*idx]   = h0;
    ((uint32_t*)hi)[2*idx+1] = h1;
    ((uint32_t*)lo)[2*idx]   = l0v;
    ((uint32_t*)lo)[2*idx+1] = l1v;
}

// ---------------------------------------------------------------------------
// common PTX macros
// ---------------------------------------------------------------------------
#define CP16(dst, src) \
    asm volatile("cp.async.cg.shared.global [%0], [%1], 16;\n" :: "r"(dst), "l"(src))
#define CP_COMMIT() asm volatile("cp.async.commit_group;\n" ::: "memory")
#define CP_WAIT(n)  asm volatile("cp.async.wait_group %0;\n" :: "n"(n) : "memory")

#define LDM_X4(r0,r1,r2,r3, addr) \
    asm volatile("ldmatrix.sync.aligned.m8n8.x4.shared.b16 {%0,%1,%2,%3}, [%4];" \
                 : "=r"(r0),"=r"(r1),"=r"(r2),"=r"(r3) : "r"(addr))
#define LDM_X2(r0,r1, addr) \
    asm volatile("ldmatrix.sync.aligned.m8n8.x2.shared.b16 {%0,%1}, [%2];" \
                 : "=r"(r0),"=r"(r1) : "r"(addr))
#define LDM_X2T(r0,r1, addr) \
    asm volatile("ldmatrix.sync.aligned.m8n8.x2.trans.shared.b16 {%0,%1}, [%2];" \
                 : "=r"(r0),"=r"(r1) : "r"(addr))

#define MMA16816(c0,c1,c2,c3, a0,a1,a2,a3, b0,b1) \
    asm volatile("mma.sync.aligned.m16n8k16.row.col.f32.bf16.bf16.f32 " \
                 "{%0,%1,%2,%3}, {%4,%5,%6,%7}, {%8,%9}, {%0,%1,%2,%3};" \
                 : "+f"(c0),"+f"(c1),"+f"(c2),"+f"(c3) \
                 : "r"(a0),"r"(a1),"r"(a2),"r"(a3),"r"(b0),"r"(b1))

// ---------------------------------------------------------------------------
// bf16x3 split GEMM (R5 structure: BK=32, 2-stage), TERM-MAJOR MMA order.
// C[m,n] = sum_k A[m,k]*W[n,k] + bias[n]
// 128x128x32 tiles, 256 threads (8 warps = 2m x 4n), warp tile 64x32.
// QKV launch: gridDim.z=3, mode=z (split-store [B,H,S,DH]); O: mode 3 fp32.
// ---------------------------------------------------------------------------
#define BM 128
#define BN 128
#define BK 32
#define LDT 40                 // bf16 per smem row (80 bytes, 5 chunks of 16B)
#define TILE_BYTES (BM*LDT*2)  // 10240
#define STAGE_BYTES (4*TILE_BYTES) // 40960

#define STAGE_LOAD(st, kb) do {                                                   \
    _Pragma("unroll")                                                             \
    for (int i_ = 0; i_ < 2; i_++) {                                              \
        int c_ = tid + (i_ << 8);                                                 \
        int r_ = c_ >> 2, k8_ = c_ & 3;                                           \
        uint32_t off_ = (uint32_t)((st) * STAGE_BYTES + r_ * (LDT*2) + k8_ * 16); \
        size_t ga_ = (size_t)(mBase + r_) * D_ + (kb) + k8_ * 8;                  \
        size_t gb_ = (size_t)(nBase + r_) * D_ + (kb) + k8_ * 8;                  \
        CP16(smBase + off_,                Ahi + ga_);                            \
        CP16(smBase + TILE_BYTES + off_,   Alo + ga_);                            \
        CP16(smBase + 2*TILE_BYTES + off_, Bhi + gb_);                            \
        CP16(smBase + 3*TILE_BYTES + off_, Blo + gb_);                            \
    }                                                                             \
    CP_COMMIT();                                                                  \
} while (0)

extern "C" __global__ __launch_bounds__(256) void gemm_bf16x3(
    const __nv_bfloat16* __restrict__ Ahi, const __nv_bfloat16* __restrict__ Alo,
    const __nv_bfloat16* __restrict__ WhiB, const __nv_bfloat16* __restrict__ WloB,
    const float* __restrict__ b0p, const float* __restrict__ b1p,
    const float* __restrict__ b2p, float* __restrict__ outp, int mode_base)
{
    extern __shared__ __nv_bfloat16 sm[];
    const int zi = blockIdx.z;
    const int mode = mode_base ? 3 : zi;
    const __nv_bfloat16* Bhi = WhiB + (size_t)zi * D_ * D_;
    const __nv_bfloat16* Blo = WloB + (size_t)zi * D_ * D_;
    const float* bias = (zi == 0) ? b0p : (zi == 1) ? b1p : b2p;

    const int tid  = threadIdx.x;
    const int wid  = tid >> 5, lane = tid & 31;
    const int wm   = wid >> 2, wn = wid & 3;
    const int mBase = blockIdx.y * BM;
    const int nBase = blockIdx.x * BN;
    const uint32_t smBase = (uint32_t)__cvta_generic_to_shared(sm);

    float c[4][4][4];
    #pragma unroll
    for (int mi = 0; mi < 4; mi++)
        #pragma unroll
        for (int ni = 0; ni < 4; ni++)
            #pragma unroll
            for (int e = 0; e < 4; e++) c[mi][ni][e] = 0.f;

    const int aRow = (lane & 7) + ((lane >> 3) & 1) * 8;
    const int aK   = (lane >> 4) * 8;
    const int bRow = lane & 7;
    const int bK   = ((lane >> 3) & 1) * 8;

    STAGE_LOAD(0, 0);

    for (int kt = 0; kt < D_ / BK; kt++) {
        if (kt + 1 < D_ / BK) {
            STAGE_LOAD((kt + 1) & 1, (kt + 1) * BK);
            CP_WAIT(1);
        } else {
            CP_WAIT(0);
        }
        __syncthreads();

        const uint32_t stBase = smBase + (uint32_t)((kt & 1) * STAGE_BYTES);
        #pragma unroll
        for (int kk = 0; kk < 2; kk++) {
            const int k0 = kk * 16;
            uint32_t ah[4][4], al[4][4], bh[4][2], bl[4][2];
            #pragma unroll
            for (int mi = 0; mi < 4; mi++) {
                int row = wm * 64 + mi * 16 + aRow;
                uint32_t off = stBase + (uint32_t)(row * LDT + k0 + aK) * 2;
                LDM_X4(ah[mi][0], ah[mi][1], ah[mi][2], ah[mi][3], off);
                LDM_X4(al[mi][0], al[mi][1], al[mi][2], al[mi][3], off + TILE_BYTES);
            }
            #pragma unroll
            for (int ni = 0; ni < 4; ni++) {
                int row = wn * 32 + ni * 8 + bRow;
                uint32_t off = stBase + 2 * TILE_BYTES +
                               (uint32_t)(row * LDT + k0 + bK) * 2;
                LDM_X2(bh[ni][0], bh[ni][1], off);
                LDM_X2(bl[ni][0], bl[ni][1], off + TILE_BYTES);
            }
            // TERM-MAJOR: 16 independent MMAs per term; dependent pairs
            // are >=16 instructions apart -> no accumulator RAW stalls.
            #pragma unroll
            for (int mi = 0; mi < 4; mi++)
                #pragma unroll
                for (int ni = 0; ni < 4; ni++)
                    MMA16816(c[mi][ni][0], c[mi][ni][1], c[mi][ni][2], c[mi][ni][3],
                             ah[mi][0], ah[mi][1], ah[mi][2], ah[mi][3],
                             bh[ni][0], bh[ni][1]);
            #pragma unroll
            for (int mi = 0; mi < 4; mi++)
                #pragma unroll
                for (int ni = 0; ni < 4; ni++)
                    MMA16816(c[mi][ni][0], c[mi][ni][1], c[mi][ni][2], c[mi][ni][3],
                             ah[mi][0], ah[mi][1], ah[mi][2], ah[mi][3],
                             bl[ni][0], bl[ni][1]);
            #pragma unroll
            for (int mi = 0; mi < 4; mi++)
                #pragma unroll
                for (int ni = 0; ni < 4; ni++)
                    MMA16816(c[mi][ni][0], c[mi][ni][1], c[mi][ni][2], c[mi][ni][3],
                             al[mi][0], al[mi][1], al[mi][2], al[mi][3],
                             bh[ni][0], bh[ni][1]);
        }
        __syncthreads();
    }

    // ---------------- epilogue ----------------
    const int g  = lane >> 2;
    const int th = lane & 3;

    if (mode == 3) {
        #pragma unroll
        for (int mi = 0; mi < 4; mi++)
            #pragma unroll
            for (int ni = 0; ni < 4; ni++) {
                int row0 = mBase + wm * 64 + mi * 16 + g;
                int col0 = nBase + wn * 32 + ni * 8 + th * 2;
                #pragma unroll
                for (int e = 0; e < 4; e++) {
                    int m = row0 + (e >> 1) * 8;
                    int n = col0 + (e & 1);
                    outp[(size_t)m * D_ + n] = c[mi][ni][e] + bias[n];
                }
            }
    } else {
        __nv_bfloat16* dhi = (mode == 0) ? g_Qhi : (mode == 1) ? g_Khi : g_Vhi;
        __nv_bfloat16* dlo = (mode == 0) ? g_Qlo : (mode == 1) ? g_Klo : g_Vlo;
        #pragma unroll
        for (int mi = 0; mi < 4; mi++)
            #pragma unroll
            for (int ni = 0; ni < 4; ni++) {
                int row0 = mBase + wm * 64 + mi * 16 + g;
                int col0 = nBase + wn * 32 + ni * 8 + th * 2;
                float b0v = bias[col0], b1v = bias[col0 + 1];
                int hh = col0 >> 6, dh = col0 & 63;
                #pragma unroll
                for (int pr = 0; pr < 2; pr++) {
                    int m = row0 + pr * 8;
                    int b = m >> 11, s = m & 2047;
                    float v0 = c[mi][ni][pr*2]   + b0v;
                    float v1 = c[mi][ni][pr*2+1] + b1v;
                    uint32_t hv, lv;
                    split2(v0, v1, hv, lv);
                    size_t idx = (((size_t)(b * H_ + hh)) * S_ + s) * DH_ + dh;
                    *(uint32_t*)&dhi[idx] = hv;
                    *(uint32_t*)&dlo[idx] = lv;
                }
            }
    }
}

// ---------------------------------------------------------------------------
// Tensor-core flash attention (causal), bf16x3, BQ=128, 8 warps,
// 3-stage K/V pipeline, one barrier per key-tile, per-warp causal skip.
// MMA loops j-outer / nt-inner (groups of 4): no accumulator RAW chains.
// ---------------------------------------------------------------------------
#define LDF 72
#define FTILEB (64*LDF*2)      // 9216 B per 64-row tile
#define QTILEB (128*LDF*2)     // 18432 B per 128-row Q tile
#define FSTAGE (4*FTILEB)      // 36864 B: Khi, Klo, Vhi, Vlo
#define FNST   3
#define FSMEM  (FNST*FSTAGE)   // 110592 B dynamic

__global__ __launch_bounds__(256) void flash_tc() {
    extern __shared__ __nv_bfloat16 fsm[];
    const uint32_t smBase = (uint32_t)__cvta_generic_to_shared(fsm);

    const int bh = blockIdx.y;
    const int Qb = blockIdx.x;
    const int q0 = Qb * 128;
    const int tid  = threadIdx.x;
    const int wq   = tid >> 5, lane = tid & 31;
    const int g    = lane >> 2, th = lane & 3;

    const size_t base = (size_t)bh * S_ * DH_;
    const __nv_bfloat16* Qh = g_Qhi + base;
    const __nv_bfloat16* Ql = g_Qlo + base;
    const __nv_bfloat16* Kh = g_Khi + base;
    const __nv_bfloat16* Kl = g_Klo + base;
    const __nv_bfloat16* Vh = g_Vhi + base;
    const __nv_bfloat16* Vl = g_Vlo + base;

    // ---- stage Q (hi+lo) into buffer 0, pull frags ----
    #pragma unroll
    for (int i = 0; i < 8; i++) {
        int c = tid + i * 256;
        int t = c >> 10, r = (c >> 3) & 127, c8 = c & 7;
        const __nv_bfloat16* src = (t ? Ql : Qh) + (size_t)(q0 + r) * DH_ + c8 * 8;
        CP16(smBase + (uint32_t)(t * QTILEB + r * (LDF*2) + c8 * 16), src);
    }
    CP_COMMIT();
    CP_WAIT(0);
    __syncthreads();

    uint32_t qh[4][4], ql[4][4];
    {
        const int aRow = lane & 15, aK = (lane >> 4) * 8;
        int row = wq * 16 + aRow;
        #pragma unroll
        for (int j = 0; j < 4; j++) {
            uint32_t off = smBase + (uint32_t)(row * LDF + j * 16 + aK) * 2;
            LDM_X4(qh[j][0], qh[j][1], qh[j][2], qh[j][3], off);
            LDM_X4(ql[j][0], ql[j][1], ql[j][2], ql[j][3], off + QTILEB);
        }
    }
    __syncthreads();   // Q frags read before tile loads overwrite buffer 0

    float m0 = -1e30f, m1 = -1e30f, l0 = 0.f, l1 = 0.f;
    float co[8][4];
    #pragma unroll
    for (int nt = 0; nt < 8; nt++)
        #pragma unroll
        for (int e = 0; e < 4; e++) co[nt][e] = 0.f;

    const int bRow  = lane & 7;
    const int bK    = ((lane >> 3) & 1) * 8;
    const int vRow0 = (lane & 7) + ((lane >> 3) & 1) * 8;
    const int wmaxq = q0 + wq * 16 + 15;

    const int NT = 2 * Qb + 2;

#define FLOAD(st, ktv) do {                                                       \
    _Pragma("unroll")                                                             \
    for (int i_ = 0; i_ < 8; i_++) {                                              \
        int c_ = tid + i_ * 256;                                                  \
        int t_ = c_ >> 9, r_ = (c_ >> 3) & 63, c8_ = c_ & 7;                      \
        const __nv_bfloat16* s_ = (t_ == 0) ? Kh : (t_ == 1) ? Kl                 \
                                 : (t_ == 2) ? Vh : Vl;                           \
        CP16(smBase + (uint32_t)((st) * FSTAGE + t_ * FTILEB                      \
                                 + r_ * (LDF*2) + c8_ * 16),                      \
             s_ + (size_t)((ktv) * 64 + r_) * DH_ + c8_ * 8);                     \
    }                                                                             \
    CP_COMMIT();                                                                  \
} while (0)

    // prologue: 2 tiles in flight
    FLOAD(0, 0);
    FLOAD(1, 1);   // NT >= 2 always

    for (int kt = 0; kt < NT; kt++) {
        CP_WAIT(1);            // tile kt landed
        __syncthreads();       // all warps past compute of kt-1

        if (kt + 2 < NT) {
            FLOAD((kt + 2) % 3, kt + 2);
        } else {
            CP_COMMIT();
        }

        if (kt * 64 <= wmaxq) {
            const uint32_t smK = smBase + (uint32_t)((kt % 3) * FSTAGE);
            const uint32_t smV = smK + 2 * FTILEB;

            // ---- S = Q K^T (bf16x3), j-outer / nt-inner ----
            float cs[8][4];
            #pragma unroll
            for (int nt = 0; nt < 8; nt++)
                #pragma unroll
                for (int e = 0; e < 4; e++) cs[nt][e] = 0.f;

            #pragma unroll
            for (int j = 0; j < 4; j++) {
                #pragma unroll
                for (int h2 = 0; h2 < 2; h2++) {
                    uint32_t kh2[4][2], kl2[4][2];
                    #pragma unroll
                    for (int t4 = 0; t4 < 4; t4++) {
                        int nt = h2 * 4 + t4;
                        uint32_t off = smK +
                            (uint32_t)((nt*8 + bRow) * LDF + j*16 + bK) * 2;
                        LDM_X2(kh2[t4][0], kh2[t4][1], off);
                        LDM_X2(kl2[t4][0], kl2[t4][1], off + FTILEB);
                    }
                    #pragma unroll
                    for (int t4 = 0; t4 < 4; t4++) {
                        int nt = h2 * 4 + t4;
                        MMA16816(cs[nt][0], cs[nt][1], cs[nt][2], cs[nt][3],
                                 qh[j][0], qh[j][1], qh[j][2], qh[j][3],
                                 kh2[t4][0], kh2[t4][1]);
                    }
                    #pragma unroll
                    for (int t4 = 0; t4 < 4; t4++) {
                        int nt = h2 * 4 + t4;
                        MMA16816(cs[nt][0], cs[nt][1], cs[nt][2], cs[nt][3],
                                 qh[j][0], qh[j][1], qh[j][2], qh[j][3],
                                 kl2[t4][0], kl2[t4][1]);
                    }
                    #pragma unroll
                    for (int t4 = 0; t4 < 4; t4++) {
                        int nt = h2 * 4 + t4;
                        MMA16816(cs[nt][0], cs[nt][1], cs[nt][2], cs[nt][3],
                                 ql[j][0], ql[j][1], ql[j][2], ql[j][3],
                                 kh2[t4][0], kh2[t4][1]);
                    }
                }
            }

            const float scale = 0.125f;
            if (kt * 64 + 63 > q0 + wq * 16) {
                #pragma unroll
                for (int nt = 0; nt < 8; nt++) {
                    int kn = kt * 64 + nt * 8 + th * 2;
                    #pragma unroll
                    for (int e = 0; e < 4; e++) {
                        int kidx = kn + (e & 1);
                        int qi   = q0 + wq * 16 + g + (e >> 1) * 8;
                        cs[nt][e] = (kidx <= qi) ? cs[nt][e] * scale : -1e30f;
                    }
                }
            } else {
                #pragma unroll
                for (int nt = 0; nt < 8; nt++)
                    #pragma unroll
                    for (int e = 0; e < 4; e++) cs[nt][e] *= scale;
            }

            float tm0 = -1e30f, tm1 = -1e30f;
            #pragma unroll
            for (int nt = 0; nt < 8; nt++) {
                tm0 = fmaxf(tm0, fmaxf(cs[nt][0], cs[nt][1]));
                tm1 = fmaxf(tm1, fmaxf(cs[nt][2], cs[nt][3]));
            }
            tm0 = fmaxf(tm0, __shfl_xor_sync(0xffffffffu, tm0, 1));
            tm0 = fmaxf(tm0, __shfl_xor_sync(0xffffffffu, tm0, 2));
            tm1 = fmaxf(tm1, __shfl_xor_sync(0xffffffffu, tm1, 1));
            tm1 = fmaxf(tm1, __shfl_xor_sync(0xffffffffu, tm1, 2));

            float mn0 = fmaxf(m0, tm0), mn1 = fmaxf(m1, tm1);
            float cr0 = __expf(m0 - mn0), cr1 = __expf(m1 - mn1);
            m0 = mn0; m1 = mn1;
            l0 *= cr0; l1 *= cr1;
            #pragma unroll
            for (int nt = 0; nt < 8; nt++) {
                co[nt][0] *= cr0; co[nt][1] *= cr0;
                co[nt][2] *= cr1; co[nt][3] *= cr1;
            }

            uint32_t ah[4][4], al[4][4];
            #pragma unroll
            for (int nt = 0; nt < 8; nt++) {
                float p0 = __expf(cs[nt][0] - m0);
                float p1 = __expf(cs[nt][1] - m0);
                float p2 = __expf(cs[nt][2] - m1);
                float p3 = __expf(cs[nt][3] - m1);
                l0 += p0 + p1;
                l1 += p2 + p3;
                int j = nt >> 1, hh = (nt & 1) * 2;
                split2(p0, p1, ah[j][hh],     al[j][hh]);      // row g,   keys k..k+1
                split2(p2, p3, ah[j][hh + 1], al[j][hh + 1]);  // row g+8, keys k..k+1
            }

            // ---- O += P V (bf16x3), j-outer / nt-inner ----
            #pragma unroll
            for (int j = 0; j < 4; j++) {
                #pragma unroll
                for (int h2 = 0; h2 < 2; h2++) {
                    uint32_t vh2[4][2], vl2[4][2];
                    #pragma unroll
                    for (int t4 = 0; t4 < 4; t4++) {
                        int nt = h2 * 4 + t4;
                        uint32_t off = smV +
                            (uint32_t)((j*16 + vRow0) * LDF + nt*8) * 2;
                        LDM_X2T(vh2[t4][0], vh2[t4][1], off);
                        LDM_X2T(vl2[t4][0], vl2[t4][1], off + FTILEB);
                    }
                    #pragma unroll
                    for (int t4 = 0; t4 < 4; t4++) {
                        int nt = h2 * 4 + t4;
                        MMA16816(co[nt][0], co[nt][1], co[nt][2], co[nt][3],
                                 ah[j][0], ah[j][1], ah[j][2], ah[j][3],
                                 vh2[t4][0], vh2[t4][1]);
                    }
                    #pragma unroll
                    for (int t4 = 0; t4 < 4; t4++) {
                        int nt = h2 * 4 + t4;
                        MMA16816(co[nt][0], co[nt][1], co[nt][2], co[nt][3],
                                 ah[j][0], ah[j][1], ah[j][2], ah[j][3],
                                 vl2[t4][0], vl2[t4][1]);
                    }
                    #pragma unroll
                    for (int t4 = 0; t4 < 4; t4++) {
                        int nt = h2 * 4 + t4;
                        MMA16816(co[nt][0], co[nt][1], co[nt][2], co[nt][3],
                                 al[j][0], al[j][1], al[j][2], al[j][3],
                                 vh2[t4][0], vh2[t4][1]);
                    }
                }
            }
        }
    }

    l0 += __shfl_xor_sync(0xffffffffu, l0, 1);
    l0 += __shfl_xor_sync(0xffffffffu, l0, 2);
    l1 += __shfl_xor_sync(0xffffffffu, l1, 1);
    l1 += __shfl_xor_sync(0xffffffffu, l1, 2);
    float inv0 = 1.f / l0, inv1 = 1.f / l1;

    const int b  = bh >> 4, hh = bh & 15;
    const int r0 = q0 + wq * 16 + g;
    #pragma unroll
    for (int nt = 0; nt < 8; nt++) {
        int dh = nt * 8 + th * 2;
        size_t i0 = ((size_t)(b * S_ + r0))     * D_ + hh * DH_ + dh;
        size_t i1 = ((size_t)(b * S_ + r0 + 8)) * D_ + hh * DH_ + dh;
        uint32_t hv, lv;
        split2(co[nt][0] * inv0, co[nt][1] * inv0, hv, lv);
        *(uint32_t*)&g_AOhi[i0] = hv;
        *(uint32_t*)&g_AOlo[i0] = lv;
        split2(co[nt][2] * inv1, co[nt][3] * inv1, hv, lv);
        *(uint32_t*)&g_AOhi[i1] = hv;
        *(uint32_t*)&g_AOlo[i1] = lv;
    }
#undef FLOAD
}

// ---------------------------------------------------------------------------
extern "C" void kernel_launch(void* const* d_in, const int* in_sizes, int n_in,
                              void* d_out, int out_size) {
    const float* x  = (const float*)d_in[0];
    const float* Wq = (const float*)d_in[1];
    const float* bq = (const float*)d_in[2];
    const float* Wk = (const float*)d_in[3];
    const float* bk = (const float*)d_in[4];
    const float* Wv = (const float*)d_in[5];
    const float* bv = (const float*)d_in[6];
    const float* Wo = (const float*)d_in[7];
    const float* bo = (const float*)d_in[8];
    float* out = (float*)d_out;

    cudaFuncSetAttribute(gemm_bf16x3, cudaFuncAttributeMaxDynamicSharedMemorySize,
                         2 * STAGE_BYTES);
    cudaFuncSetAttribute(flash_tc, cudaFuncAttributeMaxDynamicSharedMemorySize,
                         FSMEM);

    __nv_bfloat16 *xhi, *xlo, *aohi, *aolo, *whi, *wlo;
    cudaGetSymbolAddress((void**)&xhi,  g_xhi);
    cudaGetSymbolAddress((void**)&xlo,  g_xlo);
    cudaGetSymbolAddress((void**)&aohi, g_AOhi);
    cudaGetSymbolAddress((void**)&aolo, g_AOlo);
    cudaGetSymbolAddress((void**)&whi,  g_Whi);
    cudaGetSymbolAddress((void**)&wlo,  g_Wlo);

    const int ntot = NX4 + 4 * NW4;
    cvt_split_all<<<(ntot + 255) / 256, 256>>>((const float4*)x,
        (const float4*)Wq, (const float4*)Wk, (const float4*)Wv, (const float4*)Wo);

    // fused QKV projection (gridDim.z = 3)
    dim3 gq(D_ / BN, M_ / BM, 3);
    gemm_bf16x3<<<gq, 256, 2 * STAGE_BYTES>>>(xhi, xlo, whi, wlo,
                                              bq, bk, bv, nullptr, 0);

    dim3 fg(S_ / 128, B_ * H_);  // (16, 64)
    flash_tc<<<fg, 256, FSMEM>>>();

    // O projection
    dim3 go(D_ / BN, M_ / BM, 1);
    gemm_bf16x3<<<go, 256, 2 * STAGE_BYTES>>>(aohi, aolo,
        whi + 3 * (size_t)D_ * D_, wlo + 3 * (size_t)D_ * D_,
        bo, bo, bo, out, 3);
}

// round 9
// speedup vs baseline: 1.4599x; 1.3781x over previous
#include <cuda_runtime.h>
#include <cuda_fp16.h>
#include <cstdint>

#define B_  4
#define S_  2048
#define D_  1024
#define H_  16
#define DH_ 64
#define M_  (B_*S_)   // 8192

// ---------------- scratch (static __device__, no allocation) ----------------
__device__ __half g_Qhi[(size_t)M_*D_];   // [B,H,S,DH] split
__device__ __half g_Qlo[(size_t)M_*D_];
__device__ __half g_Kh [(size_t)M_*D_];   // [B,H,S,DH] single fp16
__device__ __half g_Vh [(size_t)M_*D_];
__device__ __half g_AOhi[(size_t)M_*D_]; // [B*S, D] merged heads, split
__device__ __half g_AOlo[(size_t)M_*D_];
__device__ __half g_xhi[(size_t)M_*D_];
__device__ __half g_xlo[(size_t)M_*D_];
__device__ __half g_Wh[4][(size_t)D_*D_]; // single fp16 weights

// ---------------------------------------------------------------------------
__device__ __forceinline__ void split2h(float x, float y, uint32_t& hi, uint32_t& lo) {
    __half hx = __float2half_rn(x);
    __half hy = __float2half_rn(y);
    __half lx = __float2half_rn(x - __half2float(hx));
    __half ly = __float2half_rn(y - __half2float(hy));
    __half2 Hv(hx, hy), Lv(lx, ly);
    hi = *(uint32_t*)&Hv;
    lo = *(uint32_t*)&Lv;
}
__device__ __forceinline__ uint32_t pack2h(float x, float y) {
    __half2 v(__float2half_rn(x), __float2half_rn(y));
    return *(uint32_t*)&v;
}

// ---------------------------------------------------------------------------
// fused conversion: x (2M float4) -> fp16 split; 4 weights -> single fp16
// ---------------------------------------------------------------------------
#define NX4 ((M_*D_)/4)     // 2M
#define NW4 ((D_*D_)/4)     // 256K

__global__ __launch_bounds__(256) void cvt_all(const float4* __restrict__ x,
                                               const float4* __restrict__ w0,
                                               const float4* __restrict__ w1,
                                               const float4* __restrict__ w2,
                                               const float4* __restrict__ w3) {
    int i = blockIdx.x * blockDim.x + threadIdx.x;
    if (i < NX4) {
        float4 v = x[i];
        uint32_t h0, l0v, h1, l1v;
        split2h(v.x, v.y, h0, l0v);
        split2h(v.z, v.w, h1, l1v);
        ((uint32_t*)g_xhi)[2*i]   = h0;
        ((uint32_t*)g_xhi)[2*i+1] = h1;
        ((uint32_t*)g_xlo)[2*i]   = l0v;
        ((uint32_t*)g_xlo)[2*i+1] = l1v;
    } else {
        int j = i - NX4;
        if (j >= 4 * NW4) return;
        int w = j / NW4;
        int idx = j - w * NW4;
        const float4* src = (w == 0) ? w0 : (w == 1) ? w1 : (w == 2) ? w2 : w3;
        float4 v = src[idx];
        uint32_t* dst = (uint32_t*)(g_Wh[0] + (size_t)w * D_ * D_);
        dst[2*idx]   = pack2h(v.x, v.y);
        dst[2*idx+1] = pack2h(v.z, v.w);
    }
}

// ---------------------------------------------------------------------------
// common PTX macros
// ---------------------------------------------------------------------------
#define CP16(dst, src) \
    asm volatile("cp.async.cg.shared.global [%0], [%1], 16;\n" :: "r"(dst), "l"(src))
#define CP_COMMIT() asm volatile("cp.async.commit_group;\n" ::: "memory")
#define CP_WAIT(n)  asm volatile("cp.async.wait_group %0;\n" :: "n"(n) : "memory")

#define LDM_X4(r0,r1,r2,r3, addr) \
    asm volatile("ldmatrix.sync.aligned.m8n8.x4.shared.b16 {%0,%1,%2,%3}, [%4];" \
                 : "=r"(r0),"=r"(r1),"=r"(r2),"=r"(r3) : "r"(addr))
#define LDM_X2(r0,r1, addr) \
    asm volatile("ldmatrix.sync.aligned.m8n8.x2.shared.b16 {%0,%1}, [%2];" \
                 : "=r"(r0),"=r"(r1) : "r"(addr))
#define LDM_X2T(r0,r1, addr) \
    asm volatile("ldmatrix.sync.aligned.m8n8.x2.trans.shared.b16 {%0,%1}, [%2];" \
                 : "=r"(r0),"=r"(r1) : "r"(addr))

#define MMA16816(c0,c1,c2,c3, a0,a1,a2,a3, b0,b1) \
    asm volatile("mma.sync.aligned.m16n8k16.row.col.f32.f16.f16.f32 " \
                 "{%0,%1,%2,%3}, {%4,%5,%6,%7}, {%8,%9}, {%0,%1,%2,%3};" \
                 : "+f"(c0),"+f"(c1),"+f"(c2),"+f"(c3) \
                 : "r"(a0),"r"(a1),"r"(a2),"r"(a3),"r"(b0),"r"(b1))

// ---------------------------------------------------------------------------
// fp16x2 split GEMM:  C[m,n] = sum_k A[m,k]*W[n,k] + bias[n]
// A split (hi, lo), W single fp16:  C = Ahi*W + Alo*W  (2 MMA terms).
// 128x128x32 tiles, 2-stage cp.async, 256 threads (8 warps = 2m x 4n).
// QKV launch: gridDim.z=3; mode 0 -> Q split, 1 -> K fp16, 2 -> V fp16.
// O launch: mode 3 fp32 store.
// ---------------------------------------------------------------------------
#define BM 128
#define BN 128
#define BK 32
#define LDT 40                  // fp16 per smem row (80 bytes, 5 x 16B chunks)
#define TILE_BYTES (BM*LDT*2)   // 10240
#define STAGE_BYTES (3*TILE_BYTES) // 30720: Ahi, Alo, W

#define STAGE_LOAD(st, kb) do {                                                   \
    _Pragma("unroll")                                                             \
    for (int i_ = 0; i_ < 6; i_++) {                                              \
        int c_ = tid + (i_ << 8);                                                 \
        int t_ = c_ >> 9;                                                         \
        int r_ = (c_ >> 2) & 127;                                                 \
        int k8_ = c_ & 3;                                                         \
        uint32_t dst_ = smBase + (uint32_t)((st) * STAGE_BYTES + t_ * TILE_BYTES  \
                                            + r_ * (LDT*2) + k8_ * 16);           \
        const __half* s_ = (t_ == 0) ? Ahi : (t_ == 1) ? Alo : Wp;                \
        size_t g_ = (size_t)(((t_ < 2) ? mBase : nBase) + r_) * D_                \
                    + (kb) + k8_ * 8;                                             \
        CP16(dst_, s_ + g_);                                                      \
    }                                                                             \
    CP_COMMIT();                                                                  \
} while (0)

extern "C" __global__ __launch_bounds__(256) void gemm_f16x2(
    const __half* __restrict__ Ahi, const __half* __restrict__ Alo,
    const __half* __restrict__ WB,
    const float* __restrict__ b0p, const float* __restrict__ b1p,
    const float* __restrict__ b2p, float* __restrict__ outp, int mode_base)
{
    extern __shared__ __half sm[];
    const int zi = blockIdx.z;
    const int mode = mode_base ? 3 : zi;
    const __half* Wp = WB + (size_t)zi * D_ * D_;
    const float* bias = (zi == 0) ? b0p : (zi == 1) ? b1p : b2p;

    const int tid  = threadIdx.x;
    const int wid  = tid >> 5, lane = tid & 31;
    const int wm   = wid >> 2, wn = wid & 3;
    const int mBase = blockIdx.y * BM;
    const int nBase = blockIdx.x * BN;
    const uint32_t smBase = (uint32_t)__cvta_generic_to_shared(sm);

    float c[4][4][4];
    #pragma unroll
    for (int mi = 0; mi < 4; mi++)
        #pragma unroll
        for (int ni = 0; ni < 4; ni++)
            #pragma unroll
            for (int e = 0; e < 4; e++) c[mi][ni][e] = 0.f;

    const int aRow = (lane & 7) + ((lane >> 3) & 1) * 8;
    const int aK   = (lane >> 4) * 8;
    const int bRow = lane & 7;
    const int bK   = ((lane >> 3) & 1) * 8;

    STAGE_LOAD(0, 0);

    for (int kt = 0; kt < D_ / BK; kt++) {
        if (kt + 1 < D_ / BK) {
            STAGE_LOAD((kt + 1) & 1, (kt + 1) * BK);
            CP_WAIT(1);
        } else {
            CP_WAIT(0);
        }
        __syncthreads();

        const uint32_t stBase = smBase + (uint32_t)((kt & 1) * STAGE_BYTES);
        #pragma unroll
        for (int kk = 0; kk < 2; kk++) {
            const int k0 = kk * 16;
            uint32_t ah[4][4], al[4][4], bw[4][2];
            #pragma unroll
            for (int mi = 0; mi < 4; mi++) {
                int row = wm * 64 + mi * 16 + aRow;
                uint32_t off = stBase + (uint32_t)(row * LDT + k0 + aK) * 2;
                LDM_X4(ah[mi][0], ah[mi][1], ah[mi][2], ah[mi][3], off);
                LDM_X4(al[mi][0], al[mi][1], al[mi][2], al[mi][3], off + TILE_BYTES);
            }
            #pragma unroll
            for (int ni = 0; ni < 4; ni++) {
                int row = wn * 32 + ni * 8 + bRow;
                uint32_t off = stBase + 2 * TILE_BYTES +
                               (uint32_t)(row * LDT + k0 + bK) * 2;
                LDM_X2(bw[ni][0], bw[ni][1], off);
            }
            // term-major: 16 independent MMAs per term
            #pragma unroll
            for (int mi = 0; mi < 4; mi++)
                #pragma unroll
                for (int ni = 0; ni < 4; ni++)
                    MMA16816(c[mi][ni][0], c[mi][ni][1], c[mi][ni][2], c[mi][ni][3],
                             ah[mi][0], ah[mi][1], ah[mi][2], ah[mi][3],
                             bw[ni][0], bw[ni][1]);
            #pragma unroll
            for (int mi = 0; mi < 4; mi++)
                #pragma unroll
                for (int ni = 0; ni < 4; ni++)
                    MMA16816(c[mi][ni][0], c[mi][ni][1], c[mi][ni][2], c[mi][ni][3],
                             al[mi][0], al[mi][1], al[mi][2], al[mi][3],
                             bw[ni][0], bw[ni][1]);
        }
        __syncthreads();
    }

    // ---------------- epilogue ----------------
    const int g  = lane >> 2;
    const int th = lane & 3;

    if (mode == 3) {
        #pragma unroll
        for (int mi = 0; mi < 4; mi++)
            #pragma unroll
            for (int ni = 0; ni < 4; ni++) {
                int row0 = mBase + wm * 64 + mi * 16 + g;
                int col0 = nBase + wn * 32 + ni * 8 + th * 2;
                #pragma unroll
                for (int e = 0; e < 4; e++) {
                    int m = row0 + (e >> 1) * 8;
                    int n = col0 + (e & 1);
                    outp[(size_t)m * D_ + n] = c[mi][ni][e] + bias[n];
                }
            }
    } else {
        #pragma unroll
        for (int mi = 0; mi < 4; mi++)
            #pragma unroll
            for (int ni = 0; ni < 4; ni++) {
                int row0 = mBase + wm * 64 + mi * 16 + g;
                int col0 = nBase + wn * 32 + ni * 8 + th * 2;
                float b0v = bias[col0], b1v = bias[col0 + 1];
                int hh = col0 >> 6, dh = col0 & 63;
                #pragma unroll
                for (int pr = 0; pr < 2; pr++) {
                    int m = row0 + pr * 8;
                    int b = m >> 11, s = m & 2047;
                    float v0 = c[mi][ni][pr*2]   + b0v;
                    float v1 = c[mi][ni][pr*2+1] + b1v;
                    size_t idx = (((size_t)(b * H_ + hh)) * S_ + s) * DH_ + dh;
                    if (mode == 0) {
                        uint32_t hv, lv;
                        split2h(v0, v1, hv, lv);
                        *(uint32_t*)&g_Qhi[idx] = hv;
                        *(uint32_t*)&g_Qlo[idx] = lv;
                    } else {
                        __half* dst = (mode == 1) ? g_Kh : g_Vh;
                        *(uint32_t*)&dst[idx] = pack2h(v0, v1);
                    }
                }
            }
    }
}

// ---------------------------------------------------------------------------
// Tensor-core flash attention (causal), fp16x2 split.
// S = Qhi K^T + Qlo K^T ; O += Phi V + Plo V.   BQ=128, 8 warps,
// 3-stage K/V pipeline (2 tiles/stage), one barrier per tile, causal skip.
// ---------------------------------------------------------------------------
#define LDF 72
#define FTILEB (64*LDF*2)      // 9216 B per 64-row tile
#define QTILEB (128*LDF*2)     // 18432 B per 128-row Q tile
#define FSTAGE (2*FTILEB)      // 18432 B: K, V
#define FNST   3
#define FSMEM  (FNST*FSTAGE)   // 55296 B dynamic

__global__ __launch_bounds__(256) void flash_tc() {
    extern __shared__ __half fsm[];
    const uint32_t smBase = (uint32_t)__cvta_generic_to_shared(fsm);

    const int bh = blockIdx.y;
    const int Qb = blockIdx.x;
    const int q0 = Qb * 128;
    const int tid  = threadIdx.x;
    const int wq   = tid >> 5, lane = tid & 31;
    const int g    = lane >> 2, th = lane & 3;

    const size_t base = (size_t)bh * S_ * DH_;
    const __half* Qh = g_Qhi + base;
    const __half* Ql = g_Qlo + base;
    const __half* Kp = g_Kh + base;
    const __half* Vp = g_Vh + base;

    // ---- stage Q (hi+lo = 36864 B <= 55296) into buffers 0-1, pull frags ----
    #pragma unroll
    for (int i = 0; i < 8; i++) {
        int c = tid + i * 256;
        int t = c >> 10, r = (c >> 3) & 127, c8 = c & 7;
        const __half* src = (t ? Ql : Qh) + (size_t)(q0 + r) * DH_ + c8 * 8;
        CP16(smBase + (uint32_t)(t * QTILEB + r * (LDF*2) + c8 * 16), src);
    }
    CP_COMMIT();
    CP_WAIT(0);
    __syncthreads();

    uint32_t qh[4][4], ql[4][4];
    {
        const int aRow = lane & 15, aK = (lane >> 4) * 8;
        int row = wq * 16 + aRow;
        #pragma unroll
        for (int j = 0; j < 4; j++) {
            uint32_t off = smBase + (uint32_t)(row * LDF + j * 16 + aK) * 2;
            LDM_X4(qh[j][0], qh[j][1], qh[j][2], qh[j][3], off);
            LDM_X4(ql[j][0], ql[j][1], ql[j][2], ql[j][3], off + QTILEB);
        }
    }
    __syncthreads();   // Q frags read before tile loads overwrite buffers

    float m0 = -1e30f, m1 = -1e30f, l0 = 0.f, l1 = 0.f;
    float co[8][4];
    #pragma unroll
    for (int nt = 0; nt < 8; nt++)
        #pragma unroll
        for (int e = 0; e < 4; e++) co[nt][e] = 0.f;

    const int bRow  = lane & 7;
    const int bK    = ((lane >> 3) & 1) * 8;
    const int vRow0 = (lane & 7) + ((lane >> 3) & 1) * 8;
    const int wmaxq = q0 + wq * 16 + 15;

    const int NT = 2 * Qb + 2;

#define FLOAD(st, ktv) do {                                                       \
    _Pragma("unroll")                                                             \
    for (int i_ = 0; i_ < 4; i_++) {                                              \
        int c_ = tid + i_ * 256;                                                  \
        int t_ = c_ >> 9, r_ = (c_ >> 3) & 63, c8_ = c_ & 7;                      \
        const __half* s_ = t_ ? Vp : Kp;                                          \
        CP16(smBase + (uint32_t)((st) * FSTAGE + t_ * FTILEB                      \
                                 + r_ * (LDF*2) + c8_ * 16),                      \
             s_ + (size_t)((ktv) * 64 + r_) * DH_ + c8_ * 8);                     \
    }                                                                             \
    CP_COMMIT();                                                                  \
} while (0)

    // prologue: 2 tiles in flight
    FLOAD(0, 0);
    FLOAD(1, 1);   // NT >= 2 always

    for (int kt = 0; kt < NT; kt++) {
        CP_WAIT(1);            // tile kt landed
        __syncthreads();       // all warps past compute of kt-1

        if (kt + 2 < NT) {
            FLOAD((kt + 2) % 3, kt + 2);
        } else {
            CP_COMMIT();
        }

        if (kt * 64 <= wmaxq) {
            const uint32_t smK = smBase + (uint32_t)((kt % 3) * FSTAGE);
            const uint32_t smV = smK + FTILEB;

            // ---- S = Q K^T (fp16x2), j-outer / nt-inner ----
            float cs[8][4];
            #pragma unroll
            for (int nt = 0; nt < 8; nt++)
                #pragma unroll
                for (int e = 0; e < 4; e++) cs[nt][e] = 0.f;

            #pragma unroll
            for (int j = 0; j < 4; j++) {
                #pragma unroll
                for (int h2 = 0; h2 < 2; h2++) {
                    uint32_t kf[4][2];
                    #pragma unroll
                    for (int t4 = 0; t4 < 4; t4++) {
                        int nt = h2 * 4 + t4;
                        uint32_t off = smK +
                            (uint32_t)((nt*8 + bRow) * LDF + j*16 + bK) * 2;
                        LDM_X2(kf[t4][0], kf[t4][1], off);
                    }
                    #pragma unroll
                    for (int t4 = 0; t4 < 4; t4++) {
                        int nt = h2 * 4 + t4;
                        MMA16816(cs[nt][0], cs[nt][1], cs[nt][2], cs[nt][3],
                                 qh[j][0], qh[j][1], qh[j][2], qh[j][3],
                                 kf[t4][0], kf[t4][1]);
                    }
                    #pragma unroll
                    for (int t4 = 0; t4 < 4; t4++) {
                        int nt = h2 * 4 + t4;
                        MMA16816(cs[nt][0], cs[nt][1], cs[nt][2], cs[nt][3],
                                 ql[j][0], ql[j][1], ql[j][2], ql[j][3],
                                 kf[t4][0], kf[t4][1]);
                    }
                }
            }

            const float scale = 0.125f;
            if (kt * 64 + 63 > q0 + wq * 16) {
                #pragma unroll
                for (int nt = 0; nt < 8; nt++) {
                    int kn = kt * 64 + nt * 8 + th * 2;
                    #pragma unroll
                    for (int e = 0; e < 4; e++) {
                        int kidx = kn + (e & 1);
                        int qi   = q0 + wq * 16 + g + (e >> 1) * 8;
                        cs[nt][e] = (kidx <= qi) ? cs[nt][e] * scale : -1e30f;
                    }
                }
            } else {
                #pragma unroll
                for (int nt = 0; nt < 8; nt++)
                    #pragma unroll
                    for (int e = 0; e < 4; e++) cs[nt][e] *= scale;
            }

            float tm0 = -1e30f, tm1 = -1e30f;
            #pragma unroll
            for (int nt = 0; nt < 8; nt++) {
                tm0 = fmaxf(tm0, fmaxf(cs[nt][0], cs[nt][1]));
                tm1 = fmaxf(tm1, fmaxf(cs[nt][2], cs[nt][3]));
            }
            tm0 = fmaxf(tm0, __shfl_xor_sync(0xffffffffu, tm0, 1));
            tm0 = fmaxf(tm0, __shfl_xor_sync(0xffffffffu, tm0, 2));
            tm1 = fmaxf(tm1, __shfl_xor_sync(0xffffffffu, tm1, 1));
            tm1 = fmaxf(tm1, __shfl_xor_sync(0xffffffffu, tm1, 2));

            float mn0 = fmaxf(m0, tm0), mn1 = fmaxf(m1, tm1);
            float cr0 = __expf(m0 - mn0), cr1 = __expf(m1 - mn1);
            m0 = mn0; m1 = mn1;
            l0 *= cr0; l1 *= cr1;
            #pragma unroll
            for (int nt = 0; nt < 8; nt++) {
                co[nt][0] *= cr0; co[nt][1] *= cr0;
                co[nt][2] *= cr1; co[nt][3] *= cr1;
            }

            uint32_t ph[4][4], pl[4][4];
            #pragma unroll
            for (int nt = 0; nt < 8; nt++) {
                float p0 = __expf(cs[nt][0] - m0);
                float p1 = __expf(cs[nt][1] - m0);
                float p2 = __expf(cs[nt][2] - m1);
                float p3 = __expf(cs[nt][3] - m1);
                l0 += p0 + p1;
                l1 += p2 + p3;
                int j = nt >> 1, hh = (nt & 1) * 2;
                split2h(p0, p1, ph[j][hh],     pl[j][hh]);      // row g
                split2h(p2, p3, ph[j][hh + 1], pl[j][hh + 1]);  // row g+8
            }

            // ---- O += P V (fp16x2), j-outer / nt-inner ----
            #pragma unroll
            for (int j = 0; j < 4; j++) {
                #pragma unroll
                for (int h2 = 0; h2 < 2; h2++) {
                    uint32_t vf[4][2];
                    #pragma unroll
                    for (int t4 = 0; t4 < 4; t4++) {
                        int nt = h2 * 4 + t4;
                        uint32_t off = smV +
                            (uint32_t)((j*16 + vRow0) * LDF + nt*8) * 2;
                        LDM_X2T(vf[t4][0], vf[t4][1], off);
                    }
                    #pragma unroll
                    for (int t4 = 0; t4 < 4; t4++) {
                        int nt = h2 * 4 + t4;
                        MMA16816(co[nt][0], co[nt][1], co[nt][2], co[nt][3],
                                 ph[j][0], ph[j][1], ph[j][2], ph[j][3],
                                 vf[t4][0], vf[t4][1]);
                    }
                    #pragma unroll
                    for (int t4 = 0; t4 < 4; t4++) {
                        int nt = h2 * 4 + t4;
                        MMA16816(co[nt][0], co[nt][1], co[nt][2], co[nt][3],
                                 pl[j][0], pl[j][1], pl[j][2], pl[j][3],
                                 vf[t4][0], vf[t4][1]);
                    }
                }
            }
        }
    }

    l0 += __shfl_xor_sync(0xffffffffu, l0, 1);
    l0 += __shfl_xor_sync(0xffffffffu, l0, 2);
    l1 += __shfl_xor_sync(0xffffffffu, l1, 1);
    l1 += __shfl_xor_sync(0xffffffffu, l1, 2);
    float inv0 = 1.f / l0, inv1 = 1.f / l1;

    const int b  = bh >> 4, hh = bh & 15;
    const int r0 = q0 + wq * 16 + g;
    #pragma unroll
    for (int nt = 0; nt < 8; nt++) {
        int dh = nt * 8 + th * 2;
        size_t i0 = ((size_t)(b * S_ + r0))     * D_ + hh * DH_ + dh;
        size_t i1 = ((size_t)(b * S_ + r0 + 8)) * D_ + hh * DH_ + dh;
        uint32_t hv, lv;
        split2h(co[nt][0] * inv0, co[nt][1] * inv0, hv, lv);
        *(uint32_t*)&g_AOhi[i0] = hv;
        *(uint32_t*)&g_AOlo[i0] = lv;
        split2h(co[nt][2] * inv1, co[nt][3] * inv1, hv, lv);
        *(uint32_t*)&g_AOhi[i1] = hv;
        *(uint32_t*)&g_AOlo[i1] = lv;
    }
#undef FLOAD
}

// ---------------------------------------------------------------------------
extern "C" void kernel_launch(void* const* d_in, const int* in_sizes, int n_in,
                              void* d_out, int out_size) {
    const float* x  = (const float*)d_in[0];
    const float* Wq = (const float*)d_in[1];
    const float* bq = (const float*)d_in[2];
    const float* Wk = (const float*)d_in[3];
    const float* bk = (const float*)d_in[4];
    const float* Wv = (const float*)d_in[5];
    const float* bv = (const float*)d_in[6];
    const float* Wo = (const float*)d_in[7];
    const float* bo = (const float*)d_in[8];
    float* out = (float*)d_out;

    cudaFuncSetAttribute(gemm_f16x2, cudaFuncAttributeMaxDynamicSharedMemorySize,
                         2 * STAGE_BYTES);
    cudaFuncSetAttribute(flash_tc, cudaFuncAttributeMaxDynamicSharedMemorySize,
                         FSMEM);

    __half *xhi, *xlo, *aohi, *aolo, *wh;
    cudaGetSymbolAddress((void**)&xhi,  g_xhi);
    cudaGetSymbolAddress((void**)&xlo,  g_xlo);
    cudaGetSymbolAddress((void**)&aohi, g_AOhi);
    cudaGetSymbolAddress((void**)&aolo, g_AOlo);
    cudaGetSymbolAddress((void**)&wh,   g_Wh);

    const int ntot = NX4 + 4 * NW4;
    cvt_all<<<(ntot + 255) / 256, 256>>>((const float4*)x,
        (const float4*)Wq, (const float4*)Wk, (const float4*)Wv, (const float4*)Wo);

    // fused QKV projection (gridDim.z = 3)
    dim3 gq(D_ / BN, M_ / BM, 3);
    gemm_f16x2<<<gq, 256, 2 * STAGE_BYTES>>>(xhi, xlo, wh,
                                             bq, bk, bv, nullptr, 0);

    dim3 fg(S_ / 128, B_ * H_);  // (16, 64)
    flash_tc<<<fg, 256, FSMEM>>>();

    // O projection (zi = 0 -> Wp = wh + 3*D*D via offset)
    dim3 go(D_ / BN, M_ / BM, 1);
    gemm_f16x2<<<go, 256, 2 * STAGE_BYTES>>>(aohi, aolo,
        wh + 3 * (size_t)D_ * D_, bo, bo, bo, out, 3);
}

// round 10
// speedup vs baseline: 2.4289x; 1.6637x over previous
#include <cuda_runtime.h>
#include <cuda_fp16.h>
#include <cstdint>

#define B_  4
#define S_  2048
#define D_  1024
#define H_  16
#define DH_ 64
#define M_  (B_*S_)   // 8192

// ---------------- scratch (static __device__, no allocation) ----------------
__device__ __half g_Q [(size_t)M_*D_];   // [B,H,S,DH]
__device__ __half g_K [(size_t)M_*D_];
__device__ __half g_V [(size_t)M_*D_];
__device__ __half g_AO[(size_t)M_*D_];   // [B*S, D] merged heads
__device__ __half g_xh[(size_t)M_*D_];
__device__ __half g_Wh[4][(size_t)D_*D_];

// ---------------------------------------------------------------------------
__device__ __forceinline__ uint32_t pack2h(float x, float y) {
    __half2 v(__float2half_rn(x), __float2half_rn(y));
    return *(uint32_t*)&v;
}

// ---------------------------------------------------------------------------
// fused conversion: x (2M float4) + 4 weights -> single fp16
// ---------------------------------------------------------------------------
#define NX4 ((M_*D_)/4)     // 2M
#define NW4 ((D_*D_)/4)     // 256K

__global__ __launch_bounds__(256) void cvt_all(const float4* __restrict__ x,
                                               const float4* __restrict__ w0,
                                               const float4* __restrict__ w1,
                                               const float4* __restrict__ w2,
                                               const float4* __restrict__ w3) {
    int i = blockIdx.x * blockDim.x + threadIdx.x;
    const float4* src;
    uint32_t* dst;
    int idx;
    if (i < NX4) {
        src = x; idx = i;
        dst = (uint32_t*)g_xh;
    } else {
        int j = i - NX4;
        if (j >= 4 * NW4) return;
        int w = j / NW4;
        idx = j - w * NW4;
        src = (w == 0) ? w0 : (w == 1) ? w1 : (w == 2) ? w2 : w3;
        dst = (uint32_t*)(g_Wh[0] + (size_t)w * D_ * D_);
    }
    float4 v = src[idx];
    dst[2*idx]   = pack2h(v.x, v.y);
    dst[2*idx+1] = pack2h(v.z, v.w);
}

// ---------------------------------------------------------------------------
// common PTX macros
// ---------------------------------------------------------------------------
#define CP16(dst, src) \
    asm volatile("cp.async.cg.shared.global [%0], [%1], 16;\n" :: "r"(dst), "l"(src))
#define CP_COMMIT() asm volatile("cp.async.commit_group;\n" ::: "memory")
#define CP_WAIT(n)  asm volatile("cp.async.wait_group %0;\n" :: "n"(n) : "memory")

#define LDM_X4(r0,r1,r2,r3, addr) \
    asm volatile("ldmatrix.sync.aligned.m8n8.x4.shared.b16 {%0,%1,%2,%3}, [%4];" \
                 : "=r"(r0),"=r"(r1),"=r"(r2),"=r"(r3) : "r"(addr))
#define LDM_X2(r0,r1, addr) \
    asm volatile("ldmatrix.sync.aligned.m8n8.x2.shared.b16 {%0,%1}, [%2];" \
                 : "=r"(r0),"=r"(r1) : "r"(addr))
#define LDM_X2T(r0,r1, addr) \
    asm volatile("ldmatrix.sync.aligned.m8n8.x2.trans.shared.b16 {%0,%1}, [%2];" \
                 : "=r"(r0),"=r"(r1) : "r"(addr))

#define MMA16816(c0,c1,c2,c3, a0,a1,a2,a3, b0,b1) \
    asm volatile("mma.sync.aligned.m16n8k16.row.col.f32.f16.f16.f32 " \
                 "{%0,%1,%2,%3}, {%4,%5,%6,%7}, {%8,%9}, {%0,%1,%2,%3};" \
                 : "+f"(c0),"+f"(c1),"+f"(c2),"+f"(c3) \
                 : "r"(a0),"r"(a1),"r"(a2),"r"(a3),"r"(b0),"r"(b1))

// ---------------------------------------------------------------------------
// single-fp16 GEMM:  C[m,n] = sum_k A[m,k]*W[n,k] + bias[n]
// 128x128x32 tiles, 2-stage cp.async, 256 threads (8 warps = 2m x 4n).
// QKV launch: gridDim.z=3, epilogue packs fp16 into g_{Q,K,V} [B,H,S,DH].
// O launch: mode 3 fp32 store to outp.
// ---------------------------------------------------------------------------
#define BM 128
#define BN 128
#define BK 32
#define LDT 40                  // fp16 per smem row (80 bytes, 5 x 16B chunks)
#define TILE_BYTES (BM*LDT*2)   // 10240
#define STAGE_BYTES (2*TILE_BYTES) // 20480: A, W

#define STAGE_LOAD(st, kb) do {                                                   \
    _Pragma("unroll")                                                             \
    for (int i_ = 0; i_ < 4; i_++) {                                              \
        int c_ = tid + (i_ << 8);                                                 \
        int t_ = c_ >> 9;                                                         \
        int r_ = (c_ >> 2) & 127;                                                 \
        int k8_ = c_ & 3;                                                         \
        uint32_t dst_ = smBase + (uint32_t)((st) * STAGE_BYTES + t_ * TILE_BYTES  \
                                            + r_ * (LDT*2) + k8_ * 16);           \
        const __half* s_ = t_ ? Wp : Ap;                                          \
        size_t g_ = (size_t)((t_ ? nBase : mBase) + r_) * D_ + (kb) + k8_ * 8;    \
        CP16(dst_, s_ + g_);                                                      \
    }                                                                             \
    CP_COMMIT();                                                                  \
} while (0)

extern "C" __global__ __launch_bounds__(256) void gemm_f16(
    const __half* __restrict__ Ap, const __half* __restrict__ WB,
    const float* __restrict__ b0p, const float* __restrict__ b1p,
    const float* __restrict__ b2p, float* __restrict__ outp, int mode_base)
{
    extern __shared__ __half sm[];
    const int zi = blockIdx.z;
    const int mode = mode_base ? 3 : zi;
    const __half* Wp = WB + (size_t)zi * D_ * D_;
    const float* bias = (zi == 0) ? b0p : (zi == 1) ? b1p : b2p;

    const int tid  = threadIdx.x;
    const int wid  = tid >> 5, lane = tid & 31;
    const int wm   = wid >> 2, wn = wid & 3;
    const int mBase = blockIdx.y * BM;
    const int nBase = blockIdx.x * BN;
    const uint32_t smBase = (uint32_t)__cvta_generic_to_shared(sm);

    float c[4][4][4];
    #pragma unroll
    for (int mi = 0; mi < 4; mi++)
        #pragma unroll
        for (int ni = 0; ni < 4; ni++)
            #pragma unroll
            for (int e = 0; e < 4; e++) c[mi][ni][e] = 0.f;

    const int aRow = (lane & 7) + ((lane >> 3) & 1) * 8;
    const int aK   = (lane >> 4) * 8;
    const int bRow = lane & 7;
    const int bK   = ((lane >> 3) & 1) * 8;

    STAGE_LOAD(0, 0);

    for (int kt = 0; kt < D_ / BK; kt++) {
        if (kt + 1 < D_ / BK) {
            STAGE_LOAD((kt + 1) & 1, (kt + 1) * BK);
            CP_WAIT(1);
        } else {
            CP_WAIT(0);
        }
        __syncthreads();

        const uint32_t stBase = smBase + (uint32_t)((kt & 1) * STAGE_BYTES);
        #pragma unroll
        for (int kk = 0; kk < 2; kk++) {
            const int k0 = kk * 16;
            uint32_t af[4][4], bw[4][2];
            #pragma unroll
            for (int mi = 0; mi < 4; mi++) {
                int row = wm * 64 + mi * 16 + aRow;
                uint32_t off = stBase + (uint32_t)(row * LDT + k0 + aK) * 2;
                LDM_X4(af[mi][0], af[mi][1], af[mi][2], af[mi][3], off);
            }
            #pragma unroll
            for (int ni = 0; ni < 4; ni++) {
                int row = wn * 32 + ni * 8 + bRow;
                uint32_t off = stBase + TILE_BYTES +
                               (uint32_t)(row * LDT + k0 + bK) * 2;
                LDM_X2(bw[ni][0], bw[ni][1], off);
            }
            #pragma unroll
            for (int mi = 0; mi < 4; mi++)
                #pragma unroll
                for (int ni = 0; ni < 4; ni++)
                    MMA16816(c[mi][ni][0], c[mi][ni][1], c[mi][ni][2], c[mi][ni][3],
                             af[mi][0], af[mi][1], af[mi][2], af[mi][3],
                             bw[ni][0], bw[ni][1]);
        }
        __syncthreads();
    }

    // ---------------- epilogue ----------------
    const int g  = lane >> 2;
    const int th = lane & 3;

    if (mode == 3) {
        #pragma unroll
        for (int mi = 0; mi < 4; mi++)
            #pragma unroll
            for (int ni = 0; ni < 4; ni++) {
                int row0 = mBase + wm * 64 + mi * 16 + g;
                int col0 = nBase + wn * 32 + ni * 8 + th * 2;
                #pragma unroll
                for (int e = 0; e < 4; e++) {
                    int m = row0 + (e >> 1) * 8;
                    int n = col0 + (e & 1);
                    outp[(size_t)m * D_ + n] = c[mi][ni][e] + bias[n];
                }
            }
    } else {
        __half* dst = (mode == 0) ? g_Q : (mode == 1) ? g_K : g_V;
        #pragma unroll
        for (int mi = 0; mi < 4; mi++)
            #pragma unroll
            for (int ni = 0; ni < 4; ni++) {
                int row0 = mBase + wm * 64 + mi * 16 + g;
                int col0 = nBase + wn * 32 + ni * 8 + th * 2;
                float b0v = bias[col0], b1v = bias[col0 + 1];
                int hh = col0 >> 6, dh = col0 & 63;
                #pragma unroll
                for (int pr = 0; pr < 2; pr++) {
                    int m = row0 + pr * 8;
                    int b = m >> 11, s = m & 2047;
                    float v0 = c[mi][ni][pr*2]   + b0v;
                    float v1 = c[mi][ni][pr*2+1] + b1v;
                    size_t idx = (((size_t)(b * H_ + hh)) * S_ + s) * DH_ + dh;
                    *(uint32_t*)&dst[idx] = pack2h(v0, v1);
                }
            }
    }
}

// ---------------------------------------------------------------------------
// Tensor-core flash attention (causal), single fp16.
// S = Q K^T ; O += P V.   BQ=128, 8 warps, 3-stage K/V pipeline,
// one barrier per tile, per-warp causal skip.
// ---------------------------------------------------------------------------
#define LDF 72
#define FTILEB (64*LDF*2)      // 9216 B per 64-row tile
#define QTILEB (128*LDF*2)     // 18432 B Q tile
#define FSTAGE (2*FTILEB)      // 18432 B: K, V
#define FNST   3
#define FSMEM  (FNST*FSTAGE)   // 55296 B dynamic

__global__ __launch_bounds__(256) void flash_tc() {
    extern __shared__ __half fsm[];
    const uint32_t smBase = (uint32_t)__cvta_generic_to_shared(fsm);

    const int bh = blockIdx.y;
    const int Qb = blockIdx.x;
    const int q0 = Qb * 128;
    const int tid  = threadIdx.x;
    const int wq   = tid >> 5, lane = tid & 31;
    const int g    = lane >> 2, th = lane & 3;

    const size_t base = (size_t)bh * S_ * DH_;
    const __half* Qp = g_Q + base;
    const __half* Kp = g_K + base;
    const __half* Vp = g_V + base;

    // ---- stage Q (18432 B) into buffer 0, pull frags ----
    #pragma unroll
    for (int i = 0; i < 4; i++) {
        int c = tid + i * 256;
        int r = (c >> 3) & 127, c8 = c & 7;
        CP16(smBase + (uint32_t)(r * (LDF*2) + c8 * 16),
             Qp + (size_t)(q0 + r) * DH_ + c8 * 8);
    }
    CP_COMMIT();
    CP_WAIT(0);
    __syncthreads();

    uint32_t qf[4][4];
    {
        const int aRow = lane & 15, aK = (lane >> 4) * 8;
        int row = wq * 16 + aRow;
        #pragma unroll
        for (int j = 0; j < 4; j++) {
            uint32_t off = smBase + (uint32_t)(row * LDF + j * 16 + aK) * 2;
            LDM_X4(qf[j][0], qf[j][1], qf[j][2], qf[j][3], off);
        }
    }
    __syncthreads();   // Q frags read before tile loads overwrite buffer 0

    float m0 = -1e30f, m1 = -1e30f, l0 = 0.f, l1 = 0.f;
    float co[8][4];
    #pragma unroll
    for (int nt = 0; nt < 8; nt++)
        #pragma unroll
        for (int e = 0; e < 4; e++) co[nt][e] = 0.f;

    const int bRow  = lane & 7;
    const int bK    = ((lane >> 3) & 1) * 8;
    const int vRow0 = (lane & 7) + ((lane >> 3) & 1) * 8;
    const int wmaxq = q0 + wq * 16 + 15;

    const int NT = 2 * Qb + 2;

#define FLOAD(st, ktv) do {                                                       \
    _Pragma("unroll")                                                             \
    for (int i_ = 0; i_ < 4; i_++) {                                              \
        int c_ = tid + i_ * 256;                                                  \
        int t_ = c_ >> 9, r_ = (c_ >> 3) & 63, c8_ = c_ & 7;                      \
        const __half* s_ = t_ ? Vp : Kp;                                          \
        CP16(smBase + (uint32_t)((st) * FSTAGE + t_ * FTILEB                      \
                                 + r_ * (LDF*2) + c8_ * 16),                      \
             s_ + (size_t)((ktv) * 64 + r_) * DH_ + c8_ * 8);                     \
    }                                                                             \
    CP_COMMIT();                                                                  \
} while (0)

    // prologue: 2 tiles in flight
    FLOAD(0, 0);
    FLOAD(1, 1);   // NT >= 2 always

    for (int kt = 0; kt < NT; kt++) {
        CP_WAIT(1);            // tile kt landed
        __syncthreads();       // all warps past compute of kt-1

        if (kt + 2 < NT) {
            FLOAD((kt + 2) % 3, kt + 2);
        } else {
            CP_COMMIT();
        }

        if (kt * 64 <= wmaxq) {
            const uint32_t smK = smBase + (uint32_t)((kt % 3) * FSTAGE);
            const uint32_t smV = smK + FTILEB;

            // ---- S = Q K^T, j-outer / nt-inner ----
            float cs[8][4];
            #pragma unroll
            for (int nt = 0; nt < 8; nt++)
                #pragma unroll
                for (int e = 0; e < 4; e++) cs[nt][e] = 0.f;

            #pragma unroll
            for (int j = 0; j < 4; j++) {
                #pragma unroll
                for (int h2 = 0; h2 < 2; h2++) {
                    uint32_t kf[4][2];
                    #pragma unroll
                    for (int t4 = 0; t4 < 4; t4++) {
                        int nt = h2 * 4 + t4;
                        uint32_t off = smK +
                            (uint32_t)((nt*8 + bRow) * LDF + j*16 + bK) * 2;
                        LDM_X2(kf[t4][0], kf[t4][1], off);
                    }
                    #pragma unroll
                    for (int t4 = 0; t4 < 4; t4++) {
                        int nt = h2 * 4 + t4;
                        MMA16816(cs[nt][0], cs[nt][1], cs[nt][2], cs[nt][3],
                                 qf[j][0], qf[j][1], qf[j][2], qf[j][3],
                                 kf[t4][0], kf[t4][1]);
                    }
                }
            }

            const float scale = 0.125f;
            if (kt * 64 + 63 > q0 + wq * 16) {
                #pragma unroll
                for (int nt = 0; nt < 8; nt++) {
                    int kn = kt * 64 + nt * 8 + th * 2;
                    #pragma unroll
                    for (int e = 0; e < 4; e++) {
                        int kidx = kn + (e & 1);
                        int qi   = q0 + wq * 16 + g + (e >> 1) * 8;
                        cs[nt][e] = (kidx <= qi) ? cs[nt][e] * scale : -1e30f;
                    }
                }
            } else {
                #pragma unroll
                for (int nt = 0; nt < 8; nt++)
                    #pragma unroll
                    for (int e = 0; e < 4; e++) cs[nt][e] *= scale;
            }

            float tm0 = -1e30f, tm1 = -1e30f;
            #pragma unroll
            for (int nt = 0; nt < 8; nt++) {
                tm0 = fmaxf(tm0, fmaxf(cs[nt][0], cs[nt][1]));
                tm1 = fmaxf(tm1, fmaxf(cs[nt][2], cs[nt][3]));
            }
            tm0 = fmaxf(tm0, __shfl_xor_sync(0xffffffffu, tm0, 1));
            tm0 = fmaxf(tm0, __shfl_xor_sync(0xffffffffu, tm0, 2));
            tm1 = fmaxf(tm1, __shfl_xor_sync(0xffffffffu, tm1, 1));
            tm1 = fmaxf(tm1, __shfl_xor_sync(0xffffffffu, tm1, 2));

            float mn0 = fmaxf(m0, tm0), mn1 = fmaxf(m1, tm1);
            float cr0 = __expf(m0 - mn0), cr1 = __expf(m1 - mn1);
            m0 = mn0; m1 = mn1;
            l0 *= cr0; l1 *= cr1;
            #pragma unroll
            for (int nt = 0; nt < 8; nt++) {
                co[nt][0] *= cr0; co[nt][1] *= cr0;
                co[nt][2] *= cr1; co[nt][3] *= cr1;
            }

            uint32_t pf[4][4];
            #pragma unroll
            for (int nt = 0; nt < 8; nt++) {
                float p0 = __expf(cs[nt][0] - m0);
                float p1 = __expf(cs[nt][1] - m0);
                float p2 = __expf(cs[nt][2] - m1);
                float p3 = __expf(cs[nt][3] - m1);
                l0 += p0 + p1;
                l1 += p2 + p3;
                int j = nt >> 1, hh = (nt & 1) * 2;
                pf[j][hh]     = pack2h(p0, p1);   // row g,   keys k..k+1
                pf[j][hh + 1] = pack2h(p2, p3);   // row g+8, keys k..k+1
            }

            // ---- O += P V, j-outer / nt-inner ----
            #pragma unroll
            for (int j = 0; j < 4; j++) {
                #pragma unroll
                for (int h2 = 0; h2 < 2; h2++) {
                    uint32_t vf[4][2];
                    #pragma unroll
                    for (int t4 = 0; t4 < 4; t4++) {
                        int nt = h2 * 4 + t4;
                        uint32_t off = smV +
                            (uint32_t)((j*16 + vRow0) * LDF + nt*8) * 2;
                        LDM_X2T(vf[t4][0], vf[t4][1], off);
                    }
                    #pragma unroll
                    for (int t4 = 0; t4 < 4; t4++) {
                        int nt = h2 * 4 + t4;
                        MMA16816(co[nt][0], co[nt][1], co[nt][2], co[nt][3],
                                 pf[j][0], pf[j][1], pf[j][2], pf[j][3],
                                 vf[t4][0], vf[t4][1]);
                    }
                }
            }
        }
    }

    l0 += __shfl_xor_sync(0xffffffffu, l0, 1);
    l0 += __shfl_xor_sync(0xffffffffu, l0, 2);
    l1 += __shfl_xor_sync(0xffffffffu, l1, 1);
    l1 += __shfl_xor_sync(0xffffffffu, l1, 2);
    float inv0 = 1.f / l0, inv1 = 1.f / l1;

    const int b  = bh >> 4, hh = bh & 15;
    const int r0 = q0 + wq * 16 + g;
    #pragma unroll
    for (int nt = 0; nt < 8; nt++) {
        int dh = nt * 8 + th * 2;
        size_t i0 = ((size_t)(b * S_ + r0))     * D_ + hh * DH_ + dh;
        size_t i1 = ((size_t)(b * S_ + r0 + 8)) * D_ + hh * DH_ + dh;
        *(uint32_t*)&g_AO[i0] = pack2h(co[nt][0] * inv0, co[nt][1] * inv0);
        *(uint32_t*)&g_AO[i1] = pack2h(co[nt][2] * inv1, co[nt][3] * inv1);
    }
#undef FLOAD
}

// ---------------------------------------------------------------------------
extern "C" void kernel_launch(void* const* d_in, const int* in_sizes, int n_in,
                              void* d_out, int out_size) {
    const float* x  = (const float*)d_in[0];
    const float* Wq = (const float*)d_in[1];
    const float* bq = (const float*)d_in[2];
    const float* Wk = (const float*)d_in[3];
    const float* bk = (const float*)d_in[4];
    const float* Wv = (const float*)d_in[5];
    const float* bv = (const float*)d_in[6];
    const float* Wo = (const float*)d_in[7];
    const float* bo = (const float*)d_in[8];
    float* out = (float*)d_out;

    cudaFuncSetAttribute(gemm_f16, cudaFuncAttributeMaxDynamicSharedMemorySize,
                         2 * STAGE_BYTES);
    cudaFuncSetAttribute(flash_tc, cudaFuncAttributeMaxDynamicSharedMemorySize,
                         FSMEM);

    __half *xh, *ao, *wh;
    cudaGetSymbolAddress((void**)&xh, g_xh);
    cudaGetSymbolAddress((void**)&ao, g_AO);
    cudaGetSymbolAddress((void**)&wh, g_Wh);

    const int ntot = NX4 + 4 * NW4;
    cvt_all<<<(ntot + 255) / 256, 256>>>((const float4*)x,
        (const float4*)Wq, (const float4*)Wk, (const float4*)Wv, (const float4*)Wo);

    // fused QKV projection (gridDim.z = 3)
    dim3 gq(D_ / BN, M_ / BM, 3);
    gemm_f16<<<gq, 256, 2 * STAGE_BYTES>>>(xh, wh, bq, bk, bv, nullptr, 0);

    dim3 fg(S_ / 128, B_ * H_);  // (16, 64)
    flash_tc<<<fg, 256, FSMEM>>>();

    // O projection
    dim3 go(D_ / BN, M_ / BM, 1);
    gemm_f16<<<go, 256, 2 * STAGE_BYTES>>>(ao, wh + 3 * (size_t)D_ * D_,
                                           bo, bo, bo, out, 3);
}

// round 11
// speedup vs baseline: 2.6389x; 1.0864x over previous
#include <cuda_runtime.h>
#include <cuda_fp16.h>
#include <cstdint>

#define B_  4
#define S_  2048
#define D_  1024
#define H_  16
#define DH_ 64
#define M_  (B_*S_)   // 8192

// ---------------- scratch (static __device__, no allocation) ----------------
__device__ __half g_Q [(size_t)M_*D_];   // [B,H,S,DH]
__device__ __half g_K [(size_t)M_*D_];
__device__ __half g_V [(size_t)M_*D_];
__device__ __half g_AO[(size_t)M_*D_];   // [B*S, D] merged heads
__device__ __half g_xh[(size_t)M_*D_];
__device__ __half g_Wh[4][(size_t)D_*D_];

// ---------------------------------------------------------------------------
__device__ __forceinline__ uint32_t pack2h(float x, float y) {
    __half2 v(__float2half_rn(x), __float2half_rn(y));
    return *(uint32_t*)&v;
}

// ---------------------------------------------------------------------------
// fused conversion: x (2M float4) + 4 weights -> single fp16
// ---------------------------------------------------------------------------
#define NX4 ((M_*D_)/4)     // 2M
#define NW4 ((D_*D_)/4)     // 256K

__global__ __launch_bounds__(256) void cvt_all(const float4* __restrict__ x,
                                               const float4* __restrict__ w0,
                                               const float4* __restrict__ w1,
                                               const float4* __restrict__ w2,
                                               const float4* __restrict__ w3) {
    int i = blockIdx.x * blockDim.x + threadIdx.x;
    const float4* src;
    uint32_t* dst;
    int idx;
    if (i < NX4) {
        src = x; idx = i;
        dst = (uint32_t*)g_xh;
    } else {
        int j = i - NX4;
        if (j >= 4 * NW4) return;
        int w = j / NW4;
        idx = j - w * NW4;
        src = (w == 0) ? w0 : (w == 1) ? w1 : (w == 2) ? w2 : w3;
        dst = (uint32_t*)(g_Wh[0] + (size_t)w * D_ * D_);
    }
    float4 v = src[idx];
    dst[2*idx]   = pack2h(v.x, v.y);
    dst[2*idx+1] = pack2h(v.z, v.w);
}

// ---------------------------------------------------------------------------
// common PTX macros
// ---------------------------------------------------------------------------
#define CP16(dst, src) \
    asm volatile("cp.async.cg.shared.global [%0], [%1], 16;\n" :: "r"(dst), "l"(src))
#define CP_COMMIT() asm volatile("cp.async.commit_group;\n" ::: "memory")
#define CP_WAIT(n)  asm volatile("cp.async.wait_group %0;\n" :: "n"(n) : "memory")

#define LDM_X4(r0,r1,r2,r3, addr) \
    asm volatile("ldmatrix.sync.aligned.m8n8.x4.shared.b16 {%0,%1,%2,%3}, [%4];" \
                 : "=r"(r0),"=r"(r1),"=r"(r2),"=r"(r3) : "r"(addr))
#define LDM_X4T(r0,r1,r2,r3, addr) \
    asm volatile("ldmatrix.sync.aligned.m8n8.x4.trans.shared.b16 {%0,%1,%2,%3}, [%4];" \
                 : "=r"(r0),"=r"(r1),"=r"(r2),"=r"(r3) : "r"(addr))

#define MMA16816(c0,c1,c2,c3, a0,a1,a2,a3, b0,b1) \
    asm volatile("mma.sync.aligned.m16n8k16.row.col.f32.f16.f16.f32 " \
                 "{%0,%1,%2,%3}, {%4,%5,%6,%7}, {%8,%9}, {%0,%1,%2,%3};" \
                 : "+f"(c0),"+f"(c1),"+f"(c2),"+f"(c3) \
                 : "r"(a0),"r"(a1),"r"(a2),"r"(a3),"r"(b0),"r"(b1))

// ---------------------------------------------------------------------------
// single-fp16 GEMM:  C[m,n] = sum_k A[m,k]*W[n,k] + bias[n]
// 128x128 CTA tile, BK=64 per stage (pitch 72 = conflict-free), 2-stage
// cp.async, 256 threads (8 warps = 2m x 4n), warp tile 64x32, B via x4.
// QKV launch: gridDim.z=3, epilogue packs fp16 into g_{Q,K,V} [B,H,S,DH].
// O launch: mode 3 fp32 store to outp.
// ---------------------------------------------------------------------------
#define BM 128
#define BN 128
#define GBK 64
#define LDW 72                    // fp16 per smem row (144 B = 9 x 16B, odd)
#define GTILE (128*LDW*2)         // 18432 B
#define GSTAGE (2*GTILE)          // 36864 B: A, W
#define GSMEM  (2*GSTAGE)         // 73728 B
#define GITERS (D_/GBK)           // 16

// stage loader: 2 tiles x 128 rows x 8 chunks(16B) = 2048 chunks, 256 thr x 8
#define STAGE_LOAD(st, kb) do {                                                   \
    _Pragma("unroll")                                                             \
    for (int i_ = 0; i_ < 8; i_++) {                                              \
        int c_ = tid + (i_ << 8);                                                 \
        int t_ = c_ >> 10;                                                        \
        int r_ = (c_ >> 3) & 127;                                                 \
        int c8_ = c_ & 7;                                                         \
        uint32_t dst_ = smBase + (uint32_t)((st) * GSTAGE + t_ * GTILE            \
                                            + r_ * (LDW*2) + c8_ * 16);           \
        const __half* s_ = t_ ? Wp : Ap;                                          \
        size_t g_ = (size_t)((t_ ? nBase : mBase) + r_) * D_ + (kb) + c8_ * 8;    \
        CP16(dst_, s_ + g_);                                                      \
    }                                                                             \
    CP_COMMIT();                                                                  \
} while (0)

extern "C" __global__ __launch_bounds__(256) void gemm_f16(
    const __half* __restrict__ Ap, const __half* __restrict__ WB,
    const float* __restrict__ b0p, const float* __restrict__ b1p,
    const float* __restrict__ b2p, float* __restrict__ outp, int mode_base)
{
    extern __shared__ __half sm[];
    const int zi = blockIdx.z;
    const int mode = mode_base ? 3 : zi;
    const __half* Wp = WB + (size_t)zi * D_ * D_;
    const float* bias = (zi == 0) ? b0p : (zi == 1) ? b1p : b2p;

    const int tid  = threadIdx.x;
    const int wid  = tid >> 5, lane = tid & 31;
    const int wm   = wid >> 2, wn = wid & 3;
    const int mBase = blockIdx.y * BM;
    const int nBase = blockIdx.x * BN;
    const uint32_t smBase = (uint32_t)__cvta_generic_to_shared(sm);

    float c[4][4][4];
    #pragma unroll
    for (int mi = 0; mi < 4; mi++)
        #pragma unroll
        for (int ni = 0; ni < 4; ni++)
            #pragma unroll
            for (int e = 0; e < 4; e++) c[mi][ni][e] = 0.f;

    const int aRow  = lane & 15;          // A x4: 16 rows
    const int aK    = (lane >> 4) * 8;
    const int bRow16 = lane & 15;         // B x4: 16 n-rows
    const int bK4    = (lane >> 4) * 8;

    STAGE_LOAD(0, 0);

    for (int kt = 0; kt < GITERS; kt++) {
        if (kt + 1 < GITERS) {
            STAGE_LOAD((kt + 1) & 1, (kt + 1) * GBK);
            CP_WAIT(1);
        } else {
            CP_WAIT(0);
        }
        __syncthreads();

        const uint32_t stBase = smBase + (uint32_t)((kt & 1) * GSTAGE);
        #pragma unroll
        for (int kk = 0; kk < 4; kk++) {
            const int k0 = kk * 16;
            uint32_t af[4][4], b4[2][4];
            #pragma unroll
            for (int mi = 0; mi < 4; mi++) {
                int row = wm * 64 + mi * 16 + aRow;
                uint32_t off = stBase + (uint32_t)(row * LDW + k0 + aK) * 2;
                LDM_X4(af[mi][0], af[mi][1], af[mi][2], af[mi][3], off);
            }
            #pragma unroll
            for (int ni2 = 0; ni2 < 2; ni2++) {
                int row = wn * 32 + ni2 * 16 + bRow16;
                uint32_t off = stBase + GTILE + (uint32_t)(row * LDW + k0 + bK4) * 2;
                LDM_X4(b4[ni2][0], b4[ni2][1], b4[ni2][2], b4[ni2][3], off);
            }
            // non-trans x4 fragment map: even n-tile {r0,r2}, odd {r1,r3}
            #pragma unroll
            for (int mi = 0; mi < 4; mi++)
                #pragma unroll
                for (int ni = 0; ni < 4; ni++) {
                    int ni2 = ni >> 1, par = ni & 1;
                    MMA16816(c[mi][ni][0], c[mi][ni][1], c[mi][ni][2], c[mi][ni][3],
                             af[mi][0], af[mi][1], af[mi][2], af[mi][3],
                             b4[ni2][par ? 1 : 0], b4[ni2][par ? 3 : 2]);
                }
        }
        __syncthreads();
    }

    // ---------------- epilogue ----------------
    const int g  = lane >> 2;
    const int th = lane & 3;

    if (mode == 3) {
        #pragma unroll
        for (int mi = 0; mi < 4; mi++)
            #pragma unroll
            for (int ni = 0; ni < 4; ni++) {
                int row0 = mBase + wm * 64 + mi * 16 + g;
                int col0 = nBase + wn * 32 + ni * 8 + th * 2;
                #pragma unroll
                for (int e = 0; e < 4; e++) {
                    int m = row0 + (e >> 1) * 8;
                    int n = col0 + (e & 1);
                    outp[(size_t)m * D_ + n] = c[mi][ni][e] + bias[n];
                }
            }
    } else {
        __half* dst = (mode == 0) ? g_Q : (mode == 1) ? g_K : g_V;
        #pragma unroll
        for (int mi = 0; mi < 4; mi++)
            #pragma unroll
            for (int ni = 0; ni < 4; ni++) {
                int row0 = mBase + wm * 64 + mi * 16 + g;
                int col0 = nBase + wn * 32 + ni * 8 + th * 2;
                float b0v = bias[col0], b1v = bias[col0 + 1];
                int hh = col0 >> 6, dh = col0 & 63;
                #pragma unroll
                for (int pr = 0; pr < 2; pr++) {
                    int m = row0 + pr * 8;
                    int b = m >> 11, s = m & 2047;
                    float v0 = c[mi][ni][pr*2]   + b0v;
                    float v1 = c[mi][ni][pr*2+1] + b1v;
                    size_t idx = (((size_t)(b * H_ + hh)) * S_ + s) * DH_ + dh;
                    *(uint32_t*)&dst[idx] = pack2h(v0, v1);
                }
            }
    }
}

// ---------------------------------------------------------------------------
// Tensor-core flash attention (causal), single fp16, BQ=128, 8 warps,
// 3-stage K/V pipeline, one barrier per tile, per-warp causal skip.
// K fragments via x4 (non-trans), V via x4.trans — ldsm count halved.
// ---------------------------------------------------------------------------
#define LDF 72
#define FTILEB (64*LDF*2)      // 9216 B per 64-row tile
#define FSTAGE (2*FTILEB)      // 18432 B: K, V
#define FNST   3
#define FSMEM  (FNST*FSTAGE)   // 55296 B dynamic

__global__ __launch_bounds__(256) void flash_tc() {
    extern __shared__ __half fsm[];
    const uint32_t smBase = (uint32_t)__cvta_generic_to_shared(fsm);

    const int bh = blockIdx.y;
    const int Qb = blockIdx.x;
    const int q0 = Qb * 128;
    const int tid  = threadIdx.x;
    const int wq   = tid >> 5, lane = tid & 31;
    const int g    = lane >> 2, th = lane & 3;

    const size_t base = (size_t)bh * S_ * DH_;
    const __half* Qp = g_Q + base;
    const __half* Kp = g_K + base;
    const __half* Vp = g_V + base;

    // ---- stage Q (18432 B) into buffer 0, pull frags ----
    #pragma unroll
    for (int i = 0; i < 4; i++) {
        int c = tid + i * 256;
        int r = (c >> 3) & 127, c8 = c & 7;
        CP16(smBase + (uint32_t)(r * (LDF*2) + c8 * 16),
             Qp + (size_t)(q0 + r) * DH_ + c8 * 8);
    }
    CP_COMMIT();
    CP_WAIT(0);
    __syncthreads();

    uint32_t qf[4][4];
    {
        const int aRow = lane & 15, aK = (lane >> 4) * 8;
        int row = wq * 16 + aRow;
        #pragma unroll
        for (int j = 0; j < 4; j++) {
            uint32_t off = smBase + (uint32_t)(row * LDF + j * 16 + aK) * 2;
            LDM_X4(qf[j][0], qf[j][1], qf[j][2], qf[j][3], off);
        }
    }
    __syncthreads();   // Q frags read before tile loads overwrite buffer 0

    float m0 = -1e30f, m1 = -1e30f, l0 = 0.f, l1 = 0.f;
    float co[8][4];
    #pragma unroll
    for (int nt = 0; nt < 8; nt++)
        #pragma unroll
        for (int e = 0; e < 4; e++) co[nt][e] = 0.f;

    const int r16 = lane & 15;            // x4 row index (rows / k-rows)
    const int k8  = (lane >> 4) * 8;      // x4 column offset
    const int wmaxq = q0 + wq * 16 + 15;

    const int NT = 2 * Qb + 2;

#define FLOAD(st, ktv) do {                                                       \
    _Pragma("unroll")                                                             \
    for (int i_ = 0; i_ < 4; i_++) {                                              \
        int c_ = tid + i_ * 256;                                                  \
        int t_ = c_ >> 9, r_ = (c_ >> 3) & 63, c8_ = c_ & 7;                      \
        const __half* s_ = t_ ? Vp : Kp;                                          \
        CP16(smBase + (uint32_t)((st) * FSTAGE + t_ * FTILEB                      \
                                 + r_ * (LDF*2) + c8_ * 16),                      \
             s_ + (size_t)((ktv) * 64 + r_) * DH_ + c8_ * 8);                     \
    }                                                                             \
    CP_COMMIT();                                                                  \
} while (0)

    // prologue: 2 tiles in flight
    FLOAD(0, 0);
    FLOAD(1, 1);   // NT >= 2 always

    for (int kt = 0; kt < NT; kt++) {
        CP_WAIT(1);            // tile kt landed
        __syncthreads();       // all warps past compute of kt-1

        if (kt + 2 < NT) {
            FLOAD((kt + 2) % 3, kt + 2);
        } else {
            CP_COMMIT();
        }

        if (kt * 64 <= wmaxq) {
            const uint32_t smK = smBase + (uint32_t)((kt % 3) * FSTAGE);
            const uint32_t smV = smK + FTILEB;

            // ---- S = Q K^T, j-outer, K via x4 ----
            float cs[8][4];
            #pragma unroll
            for (int nt = 0; nt < 8; nt++)
                #pragma unroll
                for (int e = 0; e < 4; e++) cs[nt][e] = 0.f;

            #pragma unroll
            for (int j = 0; j < 4; j++) {
                uint32_t k4[4][4];
                #pragma unroll
                for (int ntp = 0; ntp < 4; ntp++) {
                    uint32_t off = smK +
                        (uint32_t)((ntp*16 + r16) * LDF + j*16 + k8) * 2;
                    LDM_X4(k4[ntp][0], k4[ntp][1], k4[ntp][2], k4[ntp][3], off);
                }
                // non-trans map: even nt {r0,r2}, odd nt {r1,r3}
                #pragma unroll
                for (int nt = 0; nt < 8; nt++) {
                    int ntp = nt >> 1, par = nt & 1;
                    MMA16816(cs[nt][0], cs[nt][1], cs[nt][2], cs[nt][3],
                             qf[j][0], qf[j][1], qf[j][2], qf[j][3],
                             k4[ntp][par ? 1 : 0], k4[ntp][par ? 3 : 2]);
                }
            }

            const float scale = 0.125f;
            if (kt * 64 + 63 > q0 + wq * 16) {
                #pragma unroll
                for (int nt = 0; nt < 8; nt++) {
                    int kn = kt * 64 + nt * 8 + th * 2;
                    #pragma unroll
                    for (int e = 0; e < 4; e++) {
                        int kidx = kn + (e & 1);
                        int qi   = q0 + wq * 16 + g + (e >> 1) * 8;
                        cs[nt][e] = (kidx <= qi) ? cs[nt][e] * scale : -1e30f;
                    }
                }
            } else {
                #pragma unroll
                for (int nt = 0; nt < 8; nt++)
                    #pragma unroll
                    for (int e = 0; e < 4; e++) cs[nt][e] *= scale;
            }

            float tm0 = -1e30f, tm1 = -1e30f;
            #pragma unroll
            for (int nt = 0; nt < 8; nt++) {
                tm0 = fmaxf(tm0, fmaxf(cs[nt][0], cs[nt][1]));
                tm1 = fmaxf(tm1, fmaxf(cs[nt][2], cs[nt][3]));
            }
            tm0 = fmaxf(tm0, __shfl_xor_sync(0xffffffffu, tm0, 1));
            tm0 = fmaxf(tm0, __shfl_xor_sync(0xffffffffu, tm0, 2));
            tm1 = fmaxf(tm1, __shfl_xor_sync(0xffffffffu, tm1, 1));
            tm1 = fmaxf(tm1, __shfl_xor_sync(0xffffffffu, tm1, 2));

            float mn0 = fmaxf(m0, tm0), mn1 = fmaxf(m1, tm1);
            float cr0 = __expf(m0 - mn0), cr1 = __expf(m1 - mn1);
            m0 = mn0; m1 = mn1;
            l0 *= cr0; l1 *= cr1;
            #pragma unroll
            for (int nt = 0; nt < 8; nt++) {
                co[nt][0] *= cr0; co[nt][1] *= cr0;
                co[nt][2] *= cr1; co[nt][3] *= cr1;
            }

            uint32_t pf[4][4];
            #pragma unroll
            for (int nt = 0; nt < 8; nt++) {
                float p0 = __expf(cs[nt][0] - m0);
                float p1 = __expf(cs[nt][1] - m0);
                float p2 = __expf(cs[nt][2] - m1);
                float p3 = __expf(cs[nt][3] - m1);
                l0 += p0 + p1;
                l1 += p2 + p3;
                int j = nt >> 1, hh = (nt & 1) * 2;
                pf[j][hh]     = pack2h(p0, p1);   // row g,   keys k..k+1
                pf[j][hh + 1] = pack2h(p2, p3);   // row g+8, keys k..k+1
            }

            // ---- O += P V, j-outer, V via x4.trans ----
            #pragma unroll
            for (int j = 0; j < 4; j++) {
                uint32_t v4[4][4];
                #pragma unroll
                for (int ntp = 0; ntp < 4; ntp++) {
                    uint32_t off = smV +
                        (uint32_t)((j*16 + r16) * LDF + ntp*16 + k8) * 2;
                    LDM_X4T(v4[ntp][0], v4[ntp][1], v4[ntp][2], v4[ntp][3], off);
                }
                // trans map: even nt {r0,r1}, odd nt {r2,r3}
                #pragma unroll
                for (int nt = 0; nt < 8; nt++) {
                    int ntp = nt >> 1, par = nt & 1;
                    MMA16816(co[nt][0], co[nt][1], co[nt][2], co[nt][3],
                             pf[j][0], pf[j][1], pf[j][2], pf[j][3],
                             v4[ntp][par ? 2 : 0], v4[ntp][par ? 3 : 1]);
                }
            }
        }
    }

    l0 += __shfl_xor_sync(0xffffffffu, l0, 1);
    l0 += __shfl_xor_sync(0xffffffffu, l0, 2);
    l1 += __shfl_xor_sync(0xffffffffu, l1, 1);
    l1 += __shfl_xor_sync(0xffffffffu, l1, 2);
    float inv0 = 1.f / l0, inv1 = 1.f / l1;

    const int b  = bh >> 4, hh = bh & 15;
    const int r0 = q0 + wq * 16 + g;
    #pragma unroll
    for (int nt = 0; nt < 8; nt++) {
        int dh = nt * 8 + th * 2;
        size_t i0 = ((size_t)(b * S_ + r0))     * D_ + hh * DH_ + dh;
        size_t i1 = ((size_t)(b * S_ + r0 + 8)) * D_ + hh * DH_ + dh;
        *(uint32_t*)&g_AO[i0] = pack2h(co[nt][0] * inv0, co[nt][1] * inv0);
        *(uint32_t*)&g_AO[i1] = pack2h(co[nt][2] * inv1, co[nt][3] * inv1);
    }
#undef FLOAD
}

// ---------------------------------------------------------------------------
extern "C" void kernel_launch(void* const* d_in, const int* in_sizes, int n_in,
                              void* d_out, int out_size) {
    const float* x  = (const float*)d_in[0];
    const float* Wq = (const float*)d_in[1];
    const float* bq = (const float*)d_in[2];
    const float* Wk = (const float*)d_in[3];
    const float* bk = (const float*)d_in[4];
    const float* Wv = (const float*)d_in[5];
    const float* bv = (const float*)d_in[6];
    const float* Wo = (const float*)d_in[7];
    const float* bo = (const float*)d_in[8];
    float* out = (float*)d_out;

    cudaFuncSetAttribute(gemm_f16, cudaFuncAttributeMaxDynamicSharedMemorySize,
                         GSMEM);
    cudaFuncSetAttribute(flash_tc, cudaFuncAttributeMaxDynamicSharedMemorySize,
                         FSMEM);

    __half *xh, *ao, *wh;
    cudaGetSymbolAddress((void**)&xh, g_xh);
    cudaGetSymbolAddress((void**)&ao, g_AO);
    cudaGetSymbolAddress((void**)&wh, g_Wh);

    const int ntot = NX4 + 4 * NW4;
    cvt_all<<<(ntot + 255) / 256, 256>>>((const float4*)x,
        (const float4*)Wq, (const float4*)Wk, (const float4*)Wv, (const float4*)Wo);

    // fused QKV projection (gridDim.z = 3)
    dim3 gq(D_ / BN, M_ / BM, 3);
    gemm_f16<<<gq, 256, GSMEM>>>(xh, wh, bq, bk, bv, nullptr, 0);

    dim3 fg(S_ / 128, B_ * H_);  // (16, 64)
    flash_tc<<<fg, 256, FSMEM>>>();

    // O projection
    dim3 go(D_ / BN, M_ / BM, 1);
    gemm_f16<<<go, 256, GSMEM>>>(ao, wh + 3 * (size_t)D_ * D_,
                                 bo, bo, bo, out, 3);
}

// round 12
// speedup vs baseline: 2.6564x; 1.0066x over previous
#include <cuda_runtime.h>
#include <cuda_fp16.h>
#include <cstdint>

#define B_  4
#define S_  2048
#define D_  1024
#define H_  16
#define DH_ 64
#define M_  (B_*S_)   // 8192

// ---------------- scratch (static __device__, no allocation) ----------------
__device__ __half g_Q [(size_t)M_*D_];   // [B,H,S,DH]
__device__ __half g_K [(size_t)M_*D_];
__device__ __half g_V [(size_t)M_*D_];
__device__ __half g_AO[(size_t)M_*D_];   // [B*S, D] merged heads
__device__ __half g_xh[(size_t)M_*D_];
__device__ __half g_Wh[4][(size_t)D_*D_];

// ---------------------------------------------------------------------------
__device__ __forceinline__ uint32_t pack2h(float x, float y) {
    __half2 v(__float2half_rn(x), __float2half_rn(y));
    return *(uint32_t*)&v;
}

// ---------------------------------------------------------------------------
// fused conversion: x (2M float4) + 4 weights -> single fp16
// ---------------------------------------------------------------------------
#define NX4 ((M_*D_)/4)     // 2M
#define NW4 ((D_*D_)/4)     // 256K

__global__ __launch_bounds__(256) void cvt_all(const float4* __restrict__ x,
                                               const float4* __restrict__ w0,
                                               const float4* __restrict__ w1,
                                               const float4* __restrict__ w2,
                                               const float4* __restrict__ w3) {
    int i = blockIdx.x * blockDim.x + threadIdx.x;
    const float4* src;
    uint32_t* dst;
    int idx;
    if (i < NX4) {
        src = x; idx = i;
        dst = (uint32_t*)g_xh;
    } else {
        int j = i - NX4;
        if (j >= 4 * NW4) return;
        int w = j / NW4;
        idx = j - w * NW4;
        src = (w == 0) ? w0 : (w == 1) ? w1 : (w == 2) ? w2 : w3;
        dst = (uint32_t*)(g_Wh[0] + (size_t)w * D_ * D_);
    }
    float4 v = src[idx];
    dst[2*idx]   = pack2h(v.x, v.y);
    dst[2*idx+1] = pack2h(v.z, v.w);
}

// ---------------------------------------------------------------------------
// common PTX macros
// ---------------------------------------------------------------------------
#define CP16(dst, src) \
    asm volatile("cp.async.cg.shared.global [%0], [%1], 16;\n" :: "r"(dst), "l"(src))
#define CP_COMMIT() asm volatile("cp.async.commit_group;\n" ::: "memory")
#define CP_WAIT(n)  asm volatile("cp.async.wait_group %0;\n" :: "n"(n) : "memory")

#define LDM_X4(r0,r1,r2,r3, addr) \
    asm volatile("ldmatrix.sync.aligned.m8n8.x4.shared.b16 {%0,%1,%2,%3}, [%4];" \
                 : "=r"(r0),"=r"(r1),"=r"(r2),"=r"(r3) : "r"(addr))
#define LDM_X4T(r0,r1,r2,r3, addr) \
    asm volatile("ldmatrix.sync.aligned.m8n8.x4.trans.shared.b16 {%0,%1,%2,%3}, [%4];" \
                 : "=r"(r0),"=r"(r1),"=r"(r2),"=r"(r3) : "r"(addr))

#define MMA16816(c0,c1,c2,c3, a0,a1,a2,a3, b0,b1) \
    asm volatile("mma.sync.aligned.m16n8k16.row.col.f32.f16.f16.f32 " \
                 "{%0,%1,%2,%3}, {%4,%5,%6,%7}, {%8,%9}, {%0,%1,%2,%3};" \
                 : "+f"(c0),"+f"(c1),"+f"(c2),"+f"(c3) \
                 : "r"(a0),"r"(a1),"r"(a2),"r"(a3),"r"(b0),"r"(b1))

// ---------------------------------------------------------------------------
// single-fp16 GEMM:  C[m,n] = sum_k A[m,k]*W[n,k] + bias[n]
// 128x128 CTA tile, BK=64, 3-stage cp.async ring, ONE barrier per k-step.
// 256 threads (8 warps = 2m x 4n), warp tile 64x32, A+B via ldmatrix.x4.
// QKV launch: gridDim.z=3, epilogue packs fp16 into g_{Q,K,V} [B,H,S,DH].
// O launch: mode 3 fp32 store to outp.
// ---------------------------------------------------------------------------
#define BM 128
#define BN 128
#define GBK 64
#define LDW 72                    // fp16 per smem row (144 B = 9 x 16B, odd)
#define GTILE (128*LDW*2)         // 18432 B
#define GSTAGE (2*GTILE)          // 36864 B: A, W
#define GNST   3
#define GSMEM  (GNST*GSTAGE)      // 110592 B
#define GITERS (D_/GBK)           // 16

// stage loader: 2 tiles x 128 rows x 8 chunks(16B) = 2048 chunks, 256 thr x 8
#define STAGE_LOAD(st, kb) do {                                                   \
    _Pragma("unroll")                                                             \
    for (int i_ = 0; i_ < 8; i_++) {                                              \
        int c_ = tid + (i_ << 8);                                                 \
        int t_ = c_ >> 10;                                                        \
        int r_ = (c_ >> 3) & 127;                                                 \
        int c8_ = c_ & 7;                                                         \
        uint32_t dst_ = smBase + (uint32_t)((st) * GSTAGE + t_ * GTILE            \
                                            + r_ * (LDW*2) + c8_ * 16);           \
        const __half* s_ = t_ ? Wp : Ap;                                          \
        size_t g_ = (size_t)((t_ ? nBase : mBase) + r_) * D_ + (kb) + c8_ * 8;    \
        CP16(dst_, s_ + g_);                                                      \
    }                                                                             \
    CP_COMMIT();                                                                  \
} while (0)

extern "C" __global__ __launch_bounds__(256, 2) void gemm_f16(
    const __half* __restrict__ Ap, const __half* __restrict__ WB,
    const float* __restrict__ b0p, const float* __restrict__ b1p,
    const float* __restrict__ b2p, float* __restrict__ outp, int mode_base)
{
    extern __shared__ __half sm[];
    const int zi = blockIdx.z;
    const int mode = mode_base ? 3 : zi;
    const __half* Wp = WB + (size_t)zi * D_ * D_;
    const float* bias = (zi == 0) ? b0p : (zi == 1) ? b1p : b2p;

    const int tid  = threadIdx.x;
    const int wid  = tid >> 5, lane = tid & 31;
    const int wm   = wid >> 2, wn = wid & 3;
    const int mBase = blockIdx.y * BM;
    const int nBase = blockIdx.x * BN;
    const uint32_t smBase = (uint32_t)__cvta_generic_to_shared(sm);

    float c[4][4][4];
    #pragma unroll
    for (int mi = 0; mi < 4; mi++)
        #pragma unroll
        for (int ni = 0; ni < 4; ni++)
            #pragma unroll
            for (int e = 0; e < 4; e++) c[mi][ni][e] = 0.f;

    const int aRow  = lane & 15;          // A x4: 16 rows
    const int aK    = (lane >> 4) * 8;
    const int bRow16 = lane & 15;         // B x4: 16 n-rows
    const int bK4    = (lane >> 4) * 8;

    // prologue: 2 stages in flight
    STAGE_LOAD(0, 0);
    STAGE_LOAD(1, GBK);

    for (int kt = 0; kt < GITERS; kt++) {
        CP_WAIT(1);          // stage kt landed (2 groups outstanding at entry)
        __syncthreads();     // all warps done with kt-1 -> its buffer reusable

        if (kt + 2 < GITERS) {
            STAGE_LOAD((kt + 2) % GNST, (kt + 2) * GBK);
        } else {
            CP_COMMIT();     // keep wait-count invariant
        }

        const uint32_t stBase = smBase + (uint32_t)((kt % GNST) * GSTAGE);
        #pragma unroll
        for (int kk = 0; kk < 4; kk++) {
            const int k0 = kk * 16;
            uint32_t af[4][4], b4[2][4];
            #pragma unroll
            for (int mi = 0; mi < 4; mi++) {
                int row = wm * 64 + mi * 16 + aRow;
                uint32_t off = stBase + (uint32_t)(row * LDW + k0 + aK) * 2;
                LDM_X4(af[mi][0], af[mi][1], af[mi][2], af[mi][3], off);
            }
            #pragma unroll
            for (int ni2 = 0; ni2 < 2; ni2++) {
                int row = wn * 32 + ni2 * 16 + bRow16;
                uint32_t off = stBase + GTILE + (uint32_t)(row * LDW + k0 + bK4) * 2;
                LDM_X4(b4[ni2][0], b4[ni2][1], b4[ni2][2], b4[ni2][3], off);
            }
            // non-trans x4 fragment map: even n-tile {r0,r2}, odd {r1,r3}
            #pragma unroll
            for (int mi = 0; mi < 4; mi++)
                #pragma unroll
                for (int ni = 0; ni < 4; ni++) {
                    int ni2 = ni >> 1, par = ni & 1;
                    MMA16816(c[mi][ni][0], c[mi][ni][1], c[mi][ni][2], c[mi][ni][3],
                             af[mi][0], af[mi][1], af[mi][2], af[mi][3],
                             b4[ni2][par ? 1 : 0], b4[ni2][par ? 3 : 2]);
                }
        }
    }

    // ---------------- epilogue ----------------
    const int g  = lane >> 2;
    const int th = lane & 3;

    if (mode == 3) {
        #pragma unroll
        for (int mi = 0; mi < 4; mi++)
            #pragma unroll
            for (int ni = 0; ni < 4; ni++) {
                int row0 = mBase + wm * 64 + mi * 16 + g;
                int col0 = nBase + wn * 32 + ni * 8 + th * 2;
                #pragma unroll
                for (int e = 0; e < 4; e++) {
                    int m = row0 + (e >> 1) * 8;
                    int n = col0 + (e & 1);
                    outp[(size_t)m * D_ + n] = c[mi][ni][e] + bias[n];
                }
            }
    } else {
        __half* dst = (mode == 0) ? g_Q : (mode == 1) ? g_K : g_V;
        #pragma unroll
        for (int mi = 0; mi < 4; mi++)
            #pragma unroll
            for (int ni = 0; ni < 4; ni++) {
                int row0 = mBase + wm * 64 + mi * 16 + g;
                int col0 = nBase + wn * 32 + ni * 8 + th * 2;
                float b0v = bias[col0], b1v = bias[col0 + 1];
                int hh = col0 >> 6, dh = col0 & 63;
                #pragma unroll
                for (int pr = 0; pr < 2; pr++) {
                    int m = row0 + pr * 8;
                    int b = m >> 11, s = m & 2047;
                    float v0 = c[mi][ni][pr*2]   + b0v;
                    float v1 = c[mi][ni][pr*2+1] + b1v;
                    size_t idx = (((size_t)(b * H_ + hh)) * S_ + s) * DH_ + dh;
                    *(uint32_t*)&dst[idx] = pack2h(v0, v1);
                }
            }
    }
}

// ---------------------------------------------------------------------------
// Tensor-core flash attention (causal), single fp16, BQ=128, 8 warps,
// 3-stage K/V pipeline, one barrier per tile, per-warp causal skip.
// K via x4 (non-trans), V via x4.trans.  __launch_bounds__(256,2) caps regs
// at 128 -> 2 CTAs/SM.  Qb REVERSED (heavy CTAs launch first: LPT).
// ---------------------------------------------------------------------------
#define LDF 72
#define FTILEB (64*LDF*2)      // 9216 B per 64-row tile
#define FSTAGE (2*FTILEB)      // 18432 B: K, V
#define FNST   3
#define FSMEM  (FNST*FSTAGE)   // 55296 B dynamic

__global__ __launch_bounds__(256, 2) void flash_tc() {
    extern __shared__ __half fsm[];
    const uint32_t smBase = (uint32_t)__cvta_generic_to_shared(fsm);

    const int bh = blockIdx.y;
    const int Qb = (int)gridDim.x - 1 - (int)blockIdx.x;   // LPT: big first
    const int q0 = Qb * 128;
    const int tid  = threadIdx.x;
    const int wq   = tid >> 5, lane = tid & 31;
    const int g    = lane >> 2, th = lane & 3;

    const size_t base = (size_t)bh * S_ * DH_;
    const __half* Qp = g_Q + base;
    const __half* Kp = g_K + base;
    const __half* Vp = g_V + base;

    // ---- stage Q (18432 B) into buffer 0, pull frags ----
    #pragma unroll
    for (int i = 0; i < 4; i++) {
        int c = tid + i * 256;
        int r = (c >> 3) & 127, c8 = c & 7;
        CP16(smBase + (uint32_t)(r * (LDF*2) + c8 * 16),
             Qp + (size_t)(q0 + r) * DH_ + c8 * 8);
    }
    CP_COMMIT();
    CP_WAIT(0);
    __syncthreads();

    uint32_t qf[4][4];
    {
        const int aRow = lane & 15, aK = (lane >> 4) * 8;
        int row = wq * 16 + aRow;
        #pragma unroll
        for (int j = 0; j < 4; j++) {
            uint32_t off = smBase + (uint32_t)(row * LDF + j * 16 + aK) * 2;
            LDM_X4(qf[j][0], qf[j][1], qf[j][2], qf[j][3], off);
        }
    }
    __syncthreads();   // Q frags read before tile loads overwrite buffer 0

    float m0 = -1e30f, m1 = -1e30f, l0 = 0.f, l1 = 0.f;
    float co[8][4];
    #pragma unroll
    for (int nt = 0; nt < 8; nt++)
        #pragma unroll
        for (int e = 0; e < 4; e++) co[nt][e] = 0.f;

    const int r16 = lane & 15;            // x4 row index
    const int k8  = (lane >> 4) * 8;      // x4 column offset
    const int wmaxq = q0 + wq * 16 + 15;

    const int NT = 2 * Qb + 2;

#define FLOAD(st, ktv) do {                                                       \
    _Pragma("unroll")                                                             \
    for (int i_ = 0; i_ < 4; i_++) {                                              \
        int c_ = tid + i_ * 256;                                                  \
        int t_ = c_ >> 9, r_ = (c_ >> 3) & 63, c8_ = c_ & 7;                      \
        const __half* s_ = t_ ? Vp : Kp;                                          \
        CP16(smBase + (uint32_t)((st) * FSTAGE + t_ * FTILEB                      \
                                 + r_ * (LDF*2) + c8_ * 16),                      \
             s_ + (size_t)((ktv) * 64 + r_) * DH_ + c8_ * 8);                     \
    }                                                                             \
    CP_COMMIT();                                                                  \
} while (0)

    // prologue: 2 tiles in flight
    FLOAD(0, 0);
    FLOAD(1, 1);   // NT >= 2 always

    for (int kt = 0; kt < NT; kt++) {
        CP_WAIT(1);            // tile kt landed
        __syncthreads();       // all warps past compute of kt-1

        if (kt + 2 < NT) {
            FLOAD((kt + 2) % 3, kt + 2);
        } else {
            CP_COMMIT();
        }

        if (kt * 64 <= wmaxq) {
            const uint32_t smK = smBase + (uint32_t)((kt % 3) * FSTAGE);
            const uint32_t smV = smK + FTILEB;

            // ---- S = Q K^T, j-outer, K via x4 ----
            float cs[8][4];
            #pragma unroll
            for (int nt = 0; nt < 8; nt++)
                #pragma unroll
                for (int e = 0; e < 4; e++) cs[nt][e] = 0.f;

            #pragma unroll
            for (int j = 0; j < 4; j++) {
                uint32_t k4[4][4];
                #pragma unroll
                for (int ntp = 0; ntp < 4; ntp++) {
                    uint32_t off = smK +
                        (uint32_t)((ntp*16 + r16) * LDF + j*16 + k8) * 2;
                    LDM_X4(k4[ntp][0], k4[ntp][1], k4[ntp][2], k4[ntp][3], off);
                }
                // non-trans map: even nt {r0,r2}, odd nt {r1,r3}
                #pragma unroll
                for (int nt = 0; nt < 8; nt++) {
                    int ntp = nt >> 1, par = nt & 1;
                    MMA16816(cs[nt][0], cs[nt][1], cs[nt][2], cs[nt][3],
                             qf[j][0], qf[j][1], qf[j][2], qf[j][3],
                             k4[ntp][par ? 1 : 0], k4[ntp][par ? 3 : 2]);
                }
            }

            const float scale = 0.125f;
            if (kt * 64 + 63 > q0 + wq * 16) {
                #pragma unroll
                for (int nt = 0; nt < 8; nt++) {
                    int kn = kt * 64 + nt * 8 + th * 2;
                    #pragma unroll
                    for (int e = 0; e < 4; e++) {
                        int kidx = kn + (e & 1);
                        int qi   = q0 + wq * 16 + g + (e >> 1) * 8;
                        cs[nt][e] = (kidx <= qi) ? cs[nt][e] * scale : -1e30f;
                    }
                }
            } else {
                #pragma unroll
                for (int nt = 0; nt < 8; nt++)
                    #pragma unroll
                    for (int e = 0; e < 4; e++) cs[nt][e] *= scale;
            }

            float tm0 = -1e30f, tm1 = -1e30f;
            #pragma unroll
            for (int nt = 0; nt < 8; nt++) {
                tm0 = fmaxf(tm0, fmaxf(cs[nt][0], cs[nt][1]));
                tm1 = fmaxf(tm1, fmaxf(cs[nt][2], cs[nt][3]));
            }
            tm0 = fmaxf(tm0, __shfl_xor_sync(0xffffffffu, tm0, 1));
            tm0 = fmaxf(tm0, __shfl_xor_sync(0xffffffffu, tm0, 2));
            tm1 = fmaxf(tm1, __shfl_xor_sync(0xffffffffu, tm1, 1));
            tm1 = fmaxf(tm1, __shfl_xor_sync(0xffffffffu, tm1, 2));

            float mn0 = fmaxf(m0, tm0), mn1 = fmaxf(m1, tm1);
            float cr0 = __expf(m0 - mn0), cr1 = __expf(m1 - mn1);
            m0 = mn0; m1 = mn1;
            l0 *= cr0; l1 *= cr1;
            #pragma unroll
            for (int nt = 0; nt < 8; nt++) {
                co[nt][0] *= cr0; co[nt][1] *= cr0;
                co[nt][2] *= cr1; co[nt][3] *= cr1;
            }

            uint32_t pf[4][4];
            #pragma unroll
            for (int nt = 0; nt < 8; nt++) {
                float p0 = __expf(cs[nt][0] - m0);
                float p1 = __expf(cs[nt][1] - m0);
                float p2 = __expf(cs[nt][2] - m1);
                float p3 = __expf(cs[nt][3] - m1);
                l0 += p0 + p1;
                l1 += p2 + p3;
                int j = nt >> 1, hh = (nt & 1) * 2;
                pf[j][hh]     = pack2h(p0, p1);   // row g,   keys k..k+1
                pf[j][hh + 1] = pack2h(p2, p3);   // row g+8, keys k..k+1
            }

            // ---- O += P V, j-outer, V via x4.trans ----
            #pragma unroll
            for (int j = 0; j < 4; j++) {
                uint32_t v4[4][4];
                #pragma unroll
                for (int ntp = 0; ntp < 4; ntp++) {
                    uint32_t off = smV +
                        (uint32_t)((j*16 + r16) * LDF + ntp*16 + k8) * 2;
                    LDM_X4T(v4[ntp][0], v4[ntp][1], v4[ntp][2], v4[ntp][3], off);
                }
                // trans map: even nt {r0,r1}, odd nt {r2,r3}
                #pragma unroll
                for (int nt = 0; nt < 8; nt++) {
                    int ntp = nt >> 1, par = nt & 1;
                    MMA16816(co[nt][0], co[nt][1], co[nt][2], co[nt][3],
                             pf[j][0], pf[j][1], pf[j][2], pf[j][3],
                             v4[ntp][par ? 2 : 0], v4[ntp][par ? 3 : 1]);
                }
            }
        }
    }

    l0 += __shfl_xor_sync(0xffffffffu, l0, 1);
    l0 += __shfl_xor_sync(0xffffffffu, l0, 2);
    l1 += __shfl_xor_sync(0xffffffffu, l1, 1);
    l1 += __shfl_xor_sync(0xffffffffu, l1, 2);
    float inv0 = 1.f / l0, inv1 = 1.f / l1;

    const int b  = bh >> 4, hh = bh & 15;
    const int r0 = q0 + wq * 16 + g;
    #pragma unroll
    for (int nt = 0; nt < 8; nt++) {
        int dh = nt * 8 + th * 2;
        size_t i0 = ((size_t)(b * S_ + r0))     * D_ + hh * DH_ + dh;
        size_t i1 = ((size_t)(b * S_ + r0 + 8)) * D_ + hh * DH_ + dh;
        *(uint32_t*)&g_AO[i0] = pack2h(co[nt][0] * inv0, co[nt][1] * inv0);
        *(uint32_t*)&g_AO[i1] = pack2h(co[nt][2] * inv1, co[nt][3] * inv1);
    }
#undef FLOAD
}

// ---------------------------------------------------------------------------
extern "C" void kernel_launch(void* const* d_in, const int* in_sizes, int n_in,
                              void* d_out, int out_size) {
    const float* x  = (const float*)d_in[0];
    const float* Wq = (const float*)d_in[1];
    const float* bq = (const float*)d_in[2];
    const float* Wk = (const float*)d_in[3];
    const float* bk = (const float*)d_in[4];
    const float* Wv = (const float*)d_in[5];
    const float* bv = (const float*)d_in[6];
    const float* Wo = (const float*)d_in[7];
    const float* bo = (const float*)d_in[8];
    float* out = (float*)d_out;

    cudaFuncSetAttribute(gemm_f16, cudaFuncAttributeMaxDynamicSharedMemorySize,
                         GSMEM);
    cudaFuncSetAttribute(flash_tc, cudaFuncAttributeMaxDynamicSharedMemorySize,
                         FSMEM);

    __half *xh, *ao, *wh;
    cudaGetSymbolAddress((void**)&xh, g_xh);
    cudaGetSymbolAddress((void**)&ao, g_AO);
    cudaGetSymbolAddress((void**)&wh, g_Wh);

    const int ntot = NX4 + 4 * NW4;
    cvt_all<<<(ntot + 255) / 256, 256>>>((const float4*)x,
        (const float4*)Wq, (const float4*)Wk, (const float4*)Wv, (const float4*)Wo);

    // fused QKV projection (gridDim.z = 3)
    dim3 gq(D_ / BN, M_ / BM, 3);
    gemm_f16<<<gq, 256, GSMEM>>>(xh, wh, bq, bk, bv, nullptr, 0);

    dim3 fg(S_ / 128, B_ * H_);  // (16, 64)
    flash_tc<<<fg, 256, FSMEM>>>();

    // O projection
    dim3 go(D_ / BN, M_ / BM, 1);
    gemm_f16<<<go, 256, GSMEM>>>(ao, wh + 3 * (size_t)D_ * D_,
                                 bo, bo, bo, out, 3);
}